// round 6
// baseline (speedup 1.0000x reference)
#include <cuda_runtime.h>
#include <math.h>
#include <stdint.h>

#define Bg   512
#define NPG  256
#define Rr   51

// ---------------- device scratch ----------------
__device__ float g_tables[5][Rr][128];
__device__ float g_PG[2][Bg][128];
__device__ float g_gsum[Bg][3][512];
__device__ float g_ght[Bg][3200];
__device__ float g_htacc[4][Bg][512];
// weights pre-baked in final smem image: [j][chunk c<32][n*32 + xorgroup*4]
__device__ float g_Wt[3 * 32 * 4096];

__device__ __forceinline__ uint32_t f2tf(float x) {
    uint32_t u; asm("cvt.rna.tf32.f32 %0, %1;" : "=r"(u) : "f"(x)); return u;
}
__device__ __forceinline__ float tfhi(float x) { return __uint_as_float(f2tf(x)); }
__device__ __forceinline__ void mma_tf32(float* d, const uint32_t* a, const uint32_t* b) {
    asm volatile(
        "mma.sync.aligned.m16n8k8.row.col.f32.tf32.tf32.f32 "
        "{%0,%1,%2,%3}, {%4,%5,%6,%7}, {%8,%9}, {%0,%1,%2,%3};"
        : "+f"(d[0]), "+f"(d[1]), "+f"(d[2]), "+f"(d[3])
        : "r"(a[0]), "r"(a[1]), "r"(a[2]), "r"(a[3]), "r"(b[0]), "r"(b[1]));
}
__device__ __forceinline__ uint32_t smem_u32(const void* p) {
    uint32_t a;
    asm("{ .reg .u64 t; cvta.to.shared.u64 t, %1; cvt.u32.u64 %0, t; }" : "=r"(a) : "l"(p));
    return a;
}
__device__ __forceinline__ void cp16(uint32_t dst, const void* src) {
    asm volatile("cp.async.ca.shared.global [%0], [%1], 16;" :: "r"(dst), "l"(src));
}
#define CP_COMMIT() asm volatile("cp.async.commit_group;" ::: "memory")
#define CP_WAIT0()  asm volatile("cp.async.wait_group 0;" ::: "memory")

// quad group placement: group (g*4+qc) xored by (row&1)*4 -> conflict-free octets
__device__ __forceinline__ int qgrp(int g, int qc, int row) {
    return ((g*4 + qc) ^ ((row & 1) << 2));
}

// ---------------- kernel 1: label tables -------------------------------
__global__ void k_tables(const float* __restrict__ rel_emb,
                         const float* __restrict__ she,
                         const float* __restrict__ ste,
                         const float* __restrict__ A_w, const float* __restrict__ A_b,
                         const float* __restrict__ C_w, const float* __restrict__ C_b,
                         const float* __restrict__ E_w, const float* __restrict__ E_b)
{
    int r = blockIdx.x, t = blockIdx.y, d = threadIdx.x;
    const float* emb; const float* W; const float* bias = 0;
    switch (t) {
        case 0: emb = rel_emb; W = A_w + 512*128;  bias = A_b; break;
        case 1: emb = she;     W = C_w + 1536*128;             break;
        case 2: emb = she;     W = C_w + 1600*128; bias = C_b; break;
        case 3: emb = ste;     W = E_w + 1536*128;             break;
        default:emb = ste;     W = E_w + 1600*128; bias = E_b; break;
    }
    float acc = bias ? bias[d] : 0.f;
    for (int k = 0; k < 64; k++) acc += emb[r*64 + k] * W[k*128 + d];
    g_tables[t][r][d] = acc;
}

// ---------------- kernel 1b: bake weights into smem image ---------------
__global__ void k_prep(const float* __restrict__ A_w, const float* __restrict__ C_w,
                       const float* __restrict__ E_w)
{
    int c = blockIdx.x;   // K chunk 0..31 (16 wide)
    int j = blockIdx.y;   // path 0..2
    const float* W = (j == 0) ? A_w : ((j == 1) ? C_w : E_w);
    float* dst = g_Wt + (size_t)(j*32 + c)*4096;
    for (int t = threadIdx.x; t < 1024; t += 256) {
        int n = t & 127, gq = t >> 7;        // gq 0..7
        int g = gq >> 2, qc = gq & 3;
        int k0 = c*16 + g*8 + qc;
        float v0 = W[(size_t)k0*128 + n];
        float v1 = W[(size_t)(k0 + 4)*128 + n];
        float h0 = tfhi(v0), h1 = tfhi(v1);
        float4 q = make_float4(h0, h1, tfhi(v0 - h0), tfhi(v1 - h1));
        *(float4*)(dst + n*32 + qgrp(g, qc, n)*4) = q;
    }
}

// ---------------- kernel 2: per-graph PG terms --------------------------
__global__ void k_pg(const float* __restrict__ flat,
                     const int* __restrict__ head_ids, const int* __restrict__ tail_ids,
                     const float* __restrict__ C_w, const float* __restrict__ E_w)
{
    int path = blockIdx.z;
    const float* W = (path == 0 ? C_w : E_w) + 512*128;
    int m0 = blockIdx.y * 32, n0 = blockIdx.x * 32;
    __shared__ float As[32][33], Bs[32][33];
    __shared__ int rowA[32], rowB[32];
    int tid = threadIdx.x;
    if (tid < 32) {
        int g = m0 + tid;
        int h = head_ids[g], t = tail_ids[g];
        rowA[tid] = (path == 0) ? h : t;
        rowB[tid] = (path == 0) ? t : h;
    }
    __syncthreads();
    int tx = tid & 15, ty = tid >> 4;
    float acc[2][2] = {{0.f,0.f},{0.f,0.f}};
    for (int k0 = 0; k0 < 1024; k0 += 32) {
        for (int e = tid; e < 1024; e += 256) {
            int m = e >> 5, k = e & 31;
            int kg = k0 + k;
            int row = (kg < 512) ? rowA[m] : rowB[m];
            int kk  = (kg < 512) ? kg : kg - 512;
            As[m][k] = flat[(size_t)row*512 + kk];
        }
        for (int e = tid; e < 1024; e += 256) {
            int k = e >> 5, n = e & 31;
            Bs[k][n] = W[(size_t)(k0 + k)*128 + n0 + n];
        }
        __syncthreads();
        #pragma unroll
        for (int k = 0; k < 32; k++) {
            float a0 = As[ty*2][k], a1 = As[ty*2+1][k];
            float b0 = Bs[k][tx*2], b1 = Bs[k][tx*2+1];
            acc[0][0] += a0*b0; acc[0][1] += a0*b1;
            acc[1][0] += a1*b0; acc[1][1] += a1*b1;
        }
        __syncthreads();
    }
    #pragma unroll
    for (int i = 0; i < 2; i++)
        #pragma unroll
        for (int q = 0; q < 2; q++)
            g_PG[path][m0 + ty*2 + i][n0 + tx*2 + q] = acc[i][q];
}

// ---------------- kernel 3: fused pipeline (3xTF32, cp.async, v4 quads) -
// smem float offsets
#define A0_OFF   0
#define A1_OFF   4096
#define B0_OFF   8192
#define B1_OFF   12288
#define SW_OFF   16384
#define SB_OFF   17920
#define PG_OFF   17936
#define WSM_OFF  18192
#define NUM_OFF  19728
#define DEN_OFF  21264
#define PRJ_OFF  21280
#define LBL_OFF  21792
#define SM_FLOATS 22176

__global__ __launch_bounds__(256, 2) void k_fused_mma(
    const float* __restrict__ flat,
    const float* __restrict__ head_sister, const float* __restrict__ tail_sister,
    const int* __restrict__ t_label, const int* __restrict__ hst, const int* __restrict__ tst,
    const float* __restrict__ B_w, const float* __restrict__ B_b,
    const float* __restrict__ Dm_w, const float* __restrict__ Dm_b,
    const float* __restrict__ G_w, const float* __restrict__ G_b,
    const int* __restrict__ head_ids, const int* __restrict__ tail_ids,
    const int* __restrict__ rel_labels,
    const float* __restrict__ she, const float* __restrict__ ste)
{
    extern __shared__ float sm[];
    float* SW   = sm + SW_OFF;
    float* SB   = sm + SB_OFF;
    float* PG   = sm + PG_OFF;
    float* Wsm  = sm + WSM_OFF;
    float* NUM  = sm + NUM_OFF;
    float* DEN  = sm + DEN_OFF;
    float* PRJ  = sm + PRJ_OFF;
    int*   lbl  = (int*)(sm + LBL_OFF);
    const uint32_t su = smem_u32(sm);

    const int b    = blockIdx.x;
    const int tid  = threadIdx.x;
    const int lane = tid & 31;
    const int wid  = tid >> 5;
    const int warpM = (wid & 3) * 32;
    const int warpN = (wid >> 2) * 64;
    const int qr = lane >> 2;
    const int qc = lane & 3;

    const int fm = tid & 127;     // A-fill row
    const int fg = tid >> 7;      // A-fill group (0/1)
    const int fAoff = fm*32 + qgrp(fg, 0, fm)*4;   // qc varies; compute per qc below

    for (int i = tid; i < 512; i += 256) {
        SW[i] = B_w[i]; SW[512 + i] = Dm_w[i]; SW[1024 + i] = G_w[i];
    }
    if (tid < 12) {
        int p = tid >> 2, l = tid & 3;
        SB[tid] = (p == 0) ? B_b[l] : ((p == 1) ? Dm_b[l] : G_b[l]);
        DEN[tid] = 0.f;
    }
    PG[tid] = g_PG[tid >> 7][b][tid & 127];
    for (int i = tid; i < 1536; i += 256) NUM[i] = 0.f;
    __syncthreads();

    for (int mt = 0; mt < 2; mt++) {
        const int rowbase = b*NPG + mt*128;
        if (tid < 128) {
            lbl[tid]       = t_label[rowbase + tid];
            lbl[128 + tid] = hst[rowbase + tid];
            lbl[256 + tid] = tst[rowbase + tid];
        }
        __syncthreads();

        const float* aSrcBase = flat + (size_t)(rowbase + fm)*512 + fg*8;

        for (int j = 0; j < 3; j++) {
            float acc[2][8][4];
            #pragma unroll
            for (int mi = 0; mi < 2; mi++)
                #pragma unroll
                for (int ni = 0; ni < 8; ni++)
                    #pragma unroll
                    for (int q = 0; q < 4; q++) acc[mi][ni][q] = 0.f;

            const float* wSrc = g_Wt + (size_t)j*32*4096;

            // prologue: fill chunk 0 into buffers 0
            {
                // B via cp.async
                uint32_t dstB = su + B0_OFF*4 + tid*16;
                const float* srcB = wSrc + tid*4;
                #pragma unroll
                for (int r = 0; r < 4; r++)
                    cp16(dstB + r*4096, srcB + r*1024);
                // A direct
                float4 va = *(const float4*)(aSrcBase);
                float4 vb = *(const float4*)(aSrcBase + 4);
                float* dA = sm + A0_OFF + fm*32;
                float hx, hy;
                hx = tfhi(va.x); hy = tfhi(vb.x);
                *(float4*)(dA + qgrp(fg,0,fm)*4) = make_float4(hx, hy, tfhi(va.x-hx), tfhi(vb.x-hy));
                hx = tfhi(va.y); hy = tfhi(vb.y);
                *(float4*)(dA + qgrp(fg,1,fm)*4) = make_float4(hx, hy, tfhi(va.y-hx), tfhi(vb.y-hy));
                hx = tfhi(va.z); hy = tfhi(vb.z);
                *(float4*)(dA + qgrp(fg,2,fm)*4) = make_float4(hx, hy, tfhi(va.z-hx), tfhi(vb.z-hy));
                hx = tfhi(va.w); hy = tfhi(vb.w);
                *(float4*)(dA + qgrp(fg,3,fm)*4) = make_float4(hx, hy, tfhi(va.w-hx), tfhi(vb.w-hy));
                CP_COMMIT();
            }

            for (int c = 0; c < 32; c++) {
                const int p = c & 1;
                CP_WAIT0();
                __syncthreads();

                const bool pre = (c < 31);
                float4 va, vb;
                if (pre) {
                    // prefetch next A chunk into registers
                    va = *(const float4*)(aSrcBase + (c + 1)*16);
                    vb = *(const float4*)(aSrcBase + (c + 1)*16 + 4);
                    // issue next B copy
                    uint32_t dstB = su + (p ? B0_OFF : B1_OFF)*4 + tid*16;
                    const float* srcB = wSrc + (size_t)(c + 1)*4096 + tid*4;
                    #pragma unroll
                    for (int r = 0; r < 4; r++)
                        cp16(dstB + r*4096, srcB + r*1024);
                    CP_COMMIT();
                }

                const float* Ab = sm + (p ? A1_OFF : A0_OFF);
                const float* Bb = sm + (p ? B1_OFF : B0_OFF);

                #pragma unroll
                for (int ks = 0; ks < 2; ks++) {
                    uint32_t ah[2][4], al[2][4];
                    #pragma unroll
                    for (int mi = 0; mi < 2; mi++) {
                        int rowA = warpM + mi*16 + qr;
                        float4 vA = *(const float4*)(Ab + rowA*32 + qgrp(ks, qc, rowA)*4);
                        float4 vB = *(const float4*)(Ab + (rowA+8)*32 + qgrp(ks, qc, rowA+8)*4);
                        ah[mi][0] = __float_as_uint(vA.x); ah[mi][1] = __float_as_uint(vB.x);
                        ah[mi][2] = __float_as_uint(vA.y); ah[mi][3] = __float_as_uint(vB.y);
                        al[mi][0] = __float_as_uint(vA.z); al[mi][1] = __float_as_uint(vB.z);
                        al[mi][2] = __float_as_uint(vA.w); al[mi][3] = __float_as_uint(vB.w);
                    }
                    #pragma unroll
                    for (int ni = 0; ni < 8; ni++) {
                        int coln = warpN + ni*8 + qr;
                        float4 v = *(const float4*)(Bb + coln*32 + qgrp(ks, qc, coln)*4);
                        uint32_t bh[2] = {__float_as_uint(v.x), __float_as_uint(v.y)};
                        uint32_t bl[2] = {__float_as_uint(v.z), __float_as_uint(v.w)};
                        #pragma unroll
                        for (int mi = 0; mi < 2; mi++) {
                            mma_tf32(acc[mi][ni], ah[mi], bh);
                            mma_tf32(acc[mi][ni], al[mi], bh);
                            mma_tf32(acc[mi][ni], ah[mi], bl);
                        }
                    }
                }

                if (pre) {
                    // convert + store next A chunk into the other buffer
                    float* dA = sm + (p ? A0_OFF : A1_OFF) + fm*32;
                    float hx, hy;
                    hx = tfhi(va.x); hy = tfhi(vb.x);
                    *(float4*)(dA + qgrp(fg,0,fm)*4) = make_float4(hx, hy, tfhi(va.x-hx), tfhi(vb.x-hy));
                    hx = tfhi(va.y); hy = tfhi(vb.y);
                    *(float4*)(dA + qgrp(fg,1,fm)*4) = make_float4(hx, hy, tfhi(va.y-hx), tfhi(vb.y-hy));
                    hx = tfhi(va.z); hy = tfhi(vb.z);
                    *(float4*)(dA + qgrp(fg,2,fm)*4) = make_float4(hx, hy, tfhi(va.z-hx), tfhi(vb.z-hy));
                    hx = tfhi(va.w); hy = tfhi(vb.w);
                    *(float4*)(dA + qgrp(fg,3,fm)*4) = make_float4(hx, hy, tfhi(va.w-hx), tfhi(vb.w-hy));
                }
            }
            __syncthreads();

            // init per-row projection accumulators with bias (all 512 entries)
            {
                float bv = SB[j*4 + (tid & 3)];
                PRJ[tid]       = bv;
                PRJ[tid + 256] = bv;
            }
            __syncthreads();

            // epilogue: adds + ReLU + partial [*,4] projection, in registers
            #pragma unroll
            for (int mi = 0; mi < 2; mi++) {
                #pragma unroll
                for (int h = 0; h < 2; h++) {
                    int r = warpM + mi*16 + qr + h*8;
                    int lT = lbl[r], lH = lbl[128 + r], lS = lbl[256 + r];
                    float p0 = 0.f, p1 = 0.f, p2 = 0.f, p3 = 0.f;
                    #pragma unroll
                    for (int ni = 0; ni < 8; ni++) {
                        int col = warpN + ni*8 + qc*2;
                        float v0 = acc[mi][ni][h*2], v1 = acc[mi][ni][h*2 + 1];
                        float add0, add1;
                        if (j == 0) {
                            float2 t = *(const float2*)&g_tables[0][lT][col];
                            add0 = t.x; add1 = t.y;
                        } else if (j == 1) {
                            float2 t1 = *(const float2*)&g_tables[1][lH][col];
                            float2 t2 = *(const float2*)&g_tables[2][lT][col];
                            add0 = PG[col] + t1.x + t2.x;
                            add1 = PG[col + 1] + t1.y + t2.y;
                        } else {
                            float2 t1 = *(const float2*)&g_tables[3][lS][col];
                            float2 t2 = *(const float2*)&g_tables[4][lT][col];
                            add0 = PG[128 + col] + t1.x + t2.x;
                            add1 = PG[128 + col + 1] + t1.y + t2.y;
                        }
                        float H0 = fmaxf(v0 + add0, 0.f);
                        float H1 = fmaxf(v1 + add1, 0.f);
                        const float* w = SW + j*512 + col*4;
                        p0 += H0*w[0] + H1*w[4];
                        p1 += H0*w[1] + H1*w[5];
                        p2 += H0*w[2] + H1*w[6];
                        p3 += H0*w[3] + H1*w[7];
                    }
                    p0 += __shfl_xor_sync(0xffffffffu, p0, 1);
                    p0 += __shfl_xor_sync(0xffffffffu, p0, 2);
                    p1 += __shfl_xor_sync(0xffffffffu, p1, 1);
                    p1 += __shfl_xor_sync(0xffffffffu, p1, 2);
                    p2 += __shfl_xor_sync(0xffffffffu, p2, 1);
                    p2 += __shfl_xor_sync(0xffffffffu, p2, 2);
                    p3 += __shfl_xor_sync(0xffffffffu, p3, 1);
                    p3 += __shfl_xor_sync(0xffffffffu, p3, 2);
                    float pl = (qc == 0) ? p0 : ((qc == 1) ? p1 : ((qc == 2) ? p2 : p3));
                    atomicAdd(&PRJ[r*4 + qc], pl);
                }
            }
            __syncthreads();
            if (tid < 128) {
                int m = tid;
                float g0 = 1.f/(1.f + expf(-PRJ[m*4 + 0]));
                float g1 = 1.f/(1.f + expf(-PRJ[m*4 + 1]));
                float g2 = 1.f/(1.f + expf(-PRJ[m*4 + 2]));
                float g3 = 1.f/(1.f + expf(-PRJ[m*4 + 3]));
                if (j == 1) {
                    const float* hsv = head_sister + (size_t)(rowbase + m)*4;
                    g0 *= hsv[0]; g1 *= hsv[1]; g2 *= hsv[2]; g3 *= hsv[3];
                } else if (j == 2) {
                    const float* tsv = tail_sister + (size_t)(rowbase + m)*4;
                    g0 *= tsv[0]; g1 *= tsv[1]; g2 *= tsv[2]; g3 *= tsv[3];
                }
                float* wp = Wsm + (size_t)(j*128 + m)*4;
                wp[0] = g0; wp[1] = g1; wp[2] = g2; wp[3] = g3;
            }
            __syncthreads();
        }

        // weighted segment sums for this tile
        {
            int c0 = tid, c1 = tid + 256;
            int l0 = tid >> 7, l1 = l0 + 2;
            float s00=0,s01=0,s02=0, s10=0,s11=0,s12=0;
            for (int n = 0; n < 128; n++) {
                float v0 = flat[(size_t)(rowbase + n)*512 + c0];
                float v1 = flat[(size_t)(rowbase + n)*512 + c1];
                float w0 = Wsm[(0*128+n)*4 + l0], w1 = Wsm[(1*128+n)*4 + l0], w2 = Wsm[(2*128+n)*4 + l0];
                float x0 = Wsm[(0*128+n)*4 + l1], x1 = Wsm[(1*128+n)*4 + l1], x2 = Wsm[(2*128+n)*4 + l1];
                s00 += w0*v0; s01 += w1*v0; s02 += w2*v0;
                s10 += x0*v1; s11 += x1*v1; s12 += x2*v1;
            }
            NUM[0*512 + c0] += s00; NUM[1*512 + c0] += s01; NUM[2*512 + c0] += s02;
            NUM[0*512 + c1] += s10; NUM[1*512 + c1] += s11; NUM[2*512 + c1] += s12;
            if (tid < 12) {
                int p = tid >> 2, l = tid & 3;
                float s = 0.f;
                for (int n = 0; n < 128; n++) s += Wsm[(p*128 + n)*4 + l];
                DEN[tid] += s;
            }
        }
        __syncthreads();
    }

    // finalize means + build g_ht rows (folded k_ght)
    {
        int h = head_ids[b], t = tail_ids[b];
        int c0 = tid, c1 = tid + 256;
        int l0 = tid >> 7, l1 = l0 + 2;
        float gsum0a = NUM[0*512 + c0] / DEN[0*4 + l0];
        float gsum0b = NUM[0*512 + c1] / DEN[0*4 + l1];
        float ghsa   = NUM[1*512 + c0] / DEN[1*4 + l0];
        float ghsb   = NUM[1*512 + c1] / DEN[1*4 + l1];
        float gtsa   = NUM[2*512 + c0] / DEN[2*4 + l0];
        float gtsb   = NUM[2*512 + c1] / DEN[2*4 + l1];
        g_gsum[b][0][c0] = gsum0a; g_gsum[b][0][c1] = gsum0b;
        g_gsum[b][1][c0] = ghsa;   g_gsum[b][1][c1] = ghsb;
        g_gsum[b][2][c0] = gtsa;   g_gsum[b][2][c1] = gtsb;
        float hva = flat[(size_t)h*512 + c0], hvb = flat[(size_t)h*512 + c1];
        float tva = flat[(size_t)t*512 + c0], tvb = flat[(size_t)t*512 + c1];
        float* out = g_ght[b];
        out[c0]        = ghsa * hva;  out[c1]        = ghsb * hvb;
        out[512 + c0]  = gtsa * tva;  out[512 + c1]  = gtsb * tvb;
        out[1024 + c0] = ghsa;        out[1024 + c1] = ghsb;
        out[1536 + c0] = gtsa;        out[1536 + c1] = gtsb;
        out[2048 + c0] = hva;         out[2048 + c1] = hvb;
        out[2560 + c0] = tva;         out[2560 + c1] = tvb;
        if (tid < 64) {
            int r = rel_labels[b];
            out[3072 + tid] = she[r*64 + tid];
            out[3136 + tid] = ste[r*64 + tid];
        }
    }
}

// ---------------- kernel 4a: ht GEMM split-K (partials) -----------------
__global__ __launch_bounds__(256) void k_ht(const float* __restrict__ ht_w)
{
    __shared__ float As2[64][33], Bs2[32][65];
    int m0 = blockIdx.y*64, n0 = blockIdx.x*64, kbase = blockIdx.z*800;
    int tid = threadIdx.x, tx = tid & 15, ty = tid >> 4;
    float acc[4][4] = {};
    for (int kc = 0; kc < 25; kc++) {
        int k0 = kbase + kc*32;
        #pragma unroll
        for (int r = 0; r < 8; r++) {
            int e = r*256 + tid; int m = e >> 5, k = e & 31;
            As2[m][k] = g_ght[m0 + m][k0 + k];
        }
        #pragma unroll
        for (int r = 0; r < 8; r++) {
            int e = r*256 + tid; int k = e >> 6, n = e & 63;
            Bs2[k][n] = ht_w[(size_t)(k0 + k)*512 + n0 + n];
        }
        __syncthreads();
        #pragma unroll
        for (int k = 0; k < 32; k++) {
            float a[4], bv[4];
            #pragma unroll
            for (int i = 0; i < 4; i++) { a[i] = As2[ty*4 + i][k]; bv[i] = Bs2[k][tx*4 + i]; }
            #pragma unroll
            for (int i = 0; i < 4; i++)
                #pragma unroll
                for (int q = 0; q < 4; q++) acc[i][q] += a[i]*bv[q];
        }
        __syncthreads();
    }
    #pragma unroll
    for (int i = 0; i < 4; i++)
        #pragma unroll
        for (int q = 0; q < 4; q++)
            g_htacc[blockIdx.z][m0 + ty*4 + i][n0 + tx*4 + q] = acc[i][q];
}

// ---------------- kernel 4b: fc + out -----------------------------------
__global__ void k_final(const float* __restrict__ flat,
                        const int* __restrict__ head_ids, const int* __restrict__ tail_ids,
                        const int* __restrict__ rel_labels, const float* __restrict__ rel_emb,
                        const float* __restrict__ ht_b,
                        const float* __restrict__ fc_w, const float* __restrict__ fc_b,
                        const float* __restrict__ out_w, const float* __restrict__ out_b,
                        float* __restrict__ out)
{
    __shared__ float rep[2112];
    __shared__ float red[256][17];
    int b = blockIdx.x, tid = threadIdx.x;
    int h = head_ids[b], t = tail_ids[b];
    for (int c = tid; c < 512; c += 256) {
        rep[c]        = g_gsum[b][0][c];
        rep[512 + c]  = flat[(size_t)h*512 + c];
        rep[1024 + c] = flat[(size_t)t*512 + c];
        float s = g_htacc[0][b][c] + g_htacc[1][b][c] + g_htacc[2][b][c] + g_htacc[3][b][c];
        rep[1536 + c] = fmaxf(s + ht_b[c], 0.f);
    }
    if (tid < 64) rep[2048 + tid] = rel_emb[rel_labels[b]*64 + tid];
    __syncthreads();

    float acc[16];
    #pragma unroll
    for (int j = 0; j < 16; j++) acc[j] = 0.f;
    for (int k = tid; k < 2112; k += 256) {
        float x = rep[k];
        const float4* w = (const float4*)(fc_w + (size_t)k*16);
        #pragma unroll
        for (int v = 0; v < 4; v++) {
            float4 ww = w[v];
            acc[v*4+0] += x*ww.x; acc[v*4+1] += x*ww.y;
            acc[v*4+2] += x*ww.z; acc[v*4+3] += x*ww.w;
        }
    }
    #pragma unroll
    for (int j = 0; j < 16; j++) red[tid][j] = acc[j];
    __syncthreads();
    for (int s = 128; s >= 1; s >>= 1) {
        if (tid < s) {
            #pragma unroll
            for (int j = 0; j < 16; j++) red[tid][j] += red[tid + s][j];
        }
        __syncthreads();
    }
    if (tid == 0) {
        float o = out_b[0];
        #pragma unroll
        for (int j = 0; j < 16; j++) o += fmaxf(red[0][j] + fc_b[j], 0.f) * out_w[j];
        out[b] = o;
    }
}

// ---------------- launch ------------------------------------------------
extern "C" void kernel_launch(void* const* d_in, const int* in_sizes, int n_in,
                              void* d_out, int out_size)
{
    const float* node_repr = (const float*)d_in[0];
    const float* head_sis  = (const float*)d_in[1];
    const float* tail_sis  = (const float*)d_in[2];
    const int*   t_label   = (const int*)d_in[3];
    const int*   hstp      = (const int*)d_in[4];
    const int*   tstp      = (const int*)d_in[5];
    const int*   head_ids  = (const int*)d_in[7];
    const int*   tail_ids  = (const int*)d_in[8];
    const int*   rel_lab   = (const int*)d_in[9];
    const float* rel_emb   = (const float*)d_in[10];
    const float* she       = (const float*)d_in[11];
    const float* ste       = (const float*)d_in[12];
    const float* A_w  = (const float*)d_in[13]; const float* A_b  = (const float*)d_in[14];
    const float* B_w  = (const float*)d_in[15]; const float* B_b  = (const float*)d_in[16];
    const float* C_w  = (const float*)d_in[17]; const float* C_b  = (const float*)d_in[18];
    const float* Dm_w = (const float*)d_in[19]; const float* Dm_b = (const float*)d_in[20];
    const float* E_w  = (const float*)d_in[21]; const float* E_b  = (const float*)d_in[22];
    const float* G_w  = (const float*)d_in[23]; const float* G_b  = (const float*)d_in[24];
    const float* ht_w = (const float*)d_in[25]; const float* ht_b = (const float*)d_in[26];
    const float* fc_w = (const float*)d_in[27]; const float* fc_b = (const float*)d_in[28];
    const float* out_w= (const float*)d_in[29]; const float* out_b= (const float*)d_in[30];
    float* out = (float*)d_out;

    const int smemBytes = SM_FLOATS * 4;
    cudaFuncSetAttribute(k_fused_mma, cudaFuncAttributeMaxDynamicSharedMemorySize, smemBytes);

    k_tables<<<dim3(Rr, 5), 128>>>(rel_emb, she, ste, A_w, A_b, C_w, C_b, E_w, E_b);
    k_prep<<<dim3(32, 3), 256>>>(A_w, C_w, E_w);
    k_pg<<<dim3(4, 16, 2), 256>>>(node_repr, head_ids, tail_ids, C_w, E_w);
    k_fused_mma<<<Bg, 256, smemBytes>>>(node_repr, head_sis, tail_sis, t_label, hstp, tstp,
                                        B_w, B_b, Dm_w, Dm_b, G_w, G_b,
                                        head_ids, tail_ids, rel_lab, she, ste);
    k_ht<<<dim3(8, 8, 4), 256>>>(ht_w);
    k_final<<<Bg, 256>>>(node_repr, head_ids, tail_ids, rel_lab, rel_emb, ht_b,
                         fc_w, fc_b, out_w, out_b, out);
}

// round 7
// speedup vs baseline: 1.7858x; 1.7858x over previous
#include <cuda_runtime.h>
#include <math.h>
#include <stdint.h>

#define Bg   512
#define NPG  256
#define Rr   51

// ---------------- device scratch ----------------
__device__ float    g_tables[5][Rr][128];
__device__ float    g_PG[2][Bg][128];
__device__ float    g_gsum[Bg][3][512];
__device__ float    g_ght[Bg][3200];
__device__ float    g_htacc[4][Bg][512];
__device__ uint32_t g_Wt[3 * 128 * 512];   // [path][n][k] tf32, k-permuted

__device__ __forceinline__ uint32_t f2tf(float x) {
    uint32_t u; asm("cvt.rna.tf32.f32 %0, %1;" : "=r"(u) : "f"(x)); return u;
}
__device__ __forceinline__ void mma_tf32(float* d, const uint32_t* a, const uint32_t* b) {
    asm volatile(
        "mma.sync.aligned.m16n8k8.row.col.f32.tf32.tf32.f32 "
        "{%0,%1,%2,%3}, {%4,%5,%6,%7}, {%8,%9}, {%0,%1,%2,%3};"
        : "+f"(d[0]), "+f"(d[1]), "+f"(d[2]), "+f"(d[3])
        : "r"(a[0]), "r"(a[1]), "r"(a[2]), "r"(a[3]), "r"(b[0]), "r"(b[1]));
}

// k-permutation within a 32-wide chunk: (c, c+4) pairs become adjacent
__device__ __forceinline__ int kperm(int c) {
    return (c & ~7) + ((c & 3) << 1) + ((c >> 2) & 1);
}

// ---------------- kernel 1: label tables -------------------------------
__global__ void k_tables(const float* __restrict__ rel_emb,
                         const float* __restrict__ she,
                         const float* __restrict__ ste,
                         const float* __restrict__ A_w, const float* __restrict__ A_b,
                         const float* __restrict__ C_w, const float* __restrict__ C_b,
                         const float* __restrict__ E_w, const float* __restrict__ E_b)
{
    int r = blockIdx.x, t = blockIdx.y, d = threadIdx.x;
    const float* emb; const float* W; const float* bias = 0;
    switch (t) {
        case 0: emb = rel_emb; W = A_w + 512*128;  bias = A_b; break;
        case 1: emb = she;     W = C_w + 1536*128;             break;
        case 2: emb = she;     W = C_w + 1600*128; bias = C_b; break;
        case 3: emb = ste;     W = E_w + 1536*128;             break;
        default:emb = ste;     W = E_w + 1600*128; bias = E_b; break;
    }
    float acc = bias ? bias[d] : 0.f;
    for (int k = 0; k < 64; k++) acc += emb[r*64 + k] * W[k*128 + d];
    g_tables[t][r][d] = acc;
}

// ---------------- kernel 1b: transpose + permute + tf32 weights ---------
__global__ void k_prep(const float* __restrict__ A_w, const float* __restrict__ C_w,
                       const float* __restrict__ E_w)
{
    int c = blockIdx.x;   // K chunk 0..15
    int j = blockIdx.y;   // path 0..2
    const float* W = (j == 0) ? A_w : ((j == 1) ? C_w : E_w);
    for (int e = threadIdx.x; e < 4096; e += 256) {
        int n = e >> 5, kk = e & 31;
        g_Wt[(size_t)(j*128 + n)*512 + c*32 + kperm(kk)] =
            f2tf(W[(size_t)(c*32 + kk)*128 + n]);
    }
}

// ---------------- kernel 2: per-graph PG terms --------------------------
__global__ void k_pg(const float* __restrict__ flat,
                     const int* __restrict__ head_ids, const int* __restrict__ tail_ids,
                     const float* __restrict__ C_w, const float* __restrict__ E_w)
{
    int path = blockIdx.z;
    const float* W = (path == 0 ? C_w : E_w) + 512*128;
    int m0 = blockIdx.y * 32, n0 = blockIdx.x * 32;
    __shared__ float As[32][33], Bs[32][33];
    __shared__ int rowA[32], rowB[32];
    int tid = threadIdx.x;
    if (tid < 32) {
        int g = m0 + tid;
        int h = head_ids[g], t = tail_ids[g];
        rowA[tid] = (path == 0) ? h : t;
        rowB[tid] = (path == 0) ? t : h;
    }
    __syncthreads();
    int tx = tid & 15, ty = tid >> 4;
    float acc[2][2] = {{0.f,0.f},{0.f,0.f}};
    for (int k0 = 0; k0 < 1024; k0 += 32) {
        for (int e = tid; e < 1024; e += 256) {
            int m = e >> 5, k = e & 31;
            int kg = k0 + k;
            int row = (kg < 512) ? rowA[m] : rowB[m];
            int kk  = (kg < 512) ? kg : kg - 512;
            As[m][k] = flat[(size_t)row*512 + kk];
        }
        for (int e = tid; e < 1024; e += 256) {
            int k = e >> 5, n = e & 31;
            Bs[k][n] = W[(size_t)(k0 + k)*128 + n0 + n];
        }
        __syncthreads();
        #pragma unroll
        for (int k = 0; k < 32; k++) {
            float a0 = As[ty*2][k], a1 = As[ty*2+1][k];
            float b0 = Bs[k][tx*2], b1 = Bs[k][tx*2+1];
            acc[0][0] += a0*b0; acc[0][1] += a0*b1;
            acc[1][0] += a1*b0; acc[1][1] += a1*b1;
        }
        __syncthreads();
    }
    #pragma unroll
    for (int i = 0; i < 2; i++)
        #pragma unroll
        for (int q = 0; q < 2; q++)
            g_PG[path][m0 + ty*2 + i][n0 + tx*2 + q] = acc[i][q];
}

// ---------------- kernel 3: fused per-node pipeline (1xTF32 mma.sync) ---
// smem layout (floats)
#define AS_OFF   0        // 128*36 = 4608
#define BT_OFF   4608     // 128*36 = 4608
#define SW_OFF   9216     // 1536
#define SB_OFF   10752    // 16
#define PG_OFF   10768    // 256
#define WSM_OFF  11024    // 1536
#define NUM_OFF  12560    // 1536
#define DEN_OFF  14096    // 16
#define PRJ_OFF  14112    // 512
#define LBL_OFF  14624    // 384 (ints)
#define SM_FLOATS 15008

__global__ __launch_bounds__(256, 2) void k_fused_mma(
    const float* __restrict__ flat,
    const float* __restrict__ head_sister, const float* __restrict__ tail_sister,
    const int* __restrict__ t_label, const int* __restrict__ hst, const int* __restrict__ tst,
    const float* __restrict__ B_w, const float* __restrict__ B_b,
    const float* __restrict__ Dm_w, const float* __restrict__ Dm_b,
    const float* __restrict__ G_w, const float* __restrict__ G_b)
{
    extern __shared__ float sm[];
    float* As   = sm + AS_OFF;
    float* Bt   = sm + BT_OFF;
    float* SW   = sm + SW_OFF;
    float* SB   = sm + SB_OFF;
    float* PG   = sm + PG_OFF;
    float* Wsm  = sm + WSM_OFF;
    float* NUM  = sm + NUM_OFF;
    float* DEN  = sm + DEN_OFF;
    float* PRJ  = sm + PRJ_OFF;
    int*   lbl  = (int*)(sm + LBL_OFF);

    const int b    = blockIdx.x;
    const int tid  = threadIdx.x;
    const int lane = tid & 31;
    const int wid  = tid >> 5;
    const int warpM = (wid & 3) * 32;
    const int warpN = (wid >> 2) * 64;
    const int qr = lane >> 2;
    const int qc = lane & 3;

    for (int i = tid; i < 512; i += 256) {
        SW[i] = B_w[i]; SW[512 + i] = Dm_w[i]; SW[1024 + i] = G_w[i];
    }
    if (tid < 12) {
        int p = tid >> 2, l = tid & 3;
        SB[tid] = (p == 0) ? B_b[l] : ((p == 1) ? Dm_b[l] : G_b[l]);
        DEN[tid] = 0.f;
    }
    PG[tid] = g_PG[tid >> 7][b][tid & 127];
    for (int i = tid; i < 1536; i += 256) NUM[i] = 0.f;
    __syncthreads();

    for (int mt = 0; mt < 2; mt++) {
        const int rowbase = b*NPG + mt*128;
        if (tid < 128) {
            lbl[tid]       = t_label[rowbase + tid];
            lbl[128 + tid] = hst[rowbase + tid];
            lbl[256 + tid] = tst[rowbase + tid];
        }
        __syncthreads();

        for (int j = 0; j < 3; j++) {
            float acc[2][8][4];
            #pragma unroll
            for (int mi = 0; mi < 2; mi++)
                #pragma unroll
                for (int ni = 0; ni < 8; ni++)
                    #pragma unroll
                    for (int q = 0; q < 4; q++) acc[mi][ni][q] = 0.f;

            for (int c = 0; c < 16; c++) {
                __syncthreads();
                // A tile: 128 x 32 fp32 -> tf32, k-permuted
                #pragma unroll
                for (int r = 0; r < 4; r++) {
                    int e = r*256 + tid;
                    int m = e >> 3, q = e & 7;
                    float4 v = *(const float4*)(flat + (size_t)(rowbase + m)*512 + c*32 + q*4);
                    int base = m*36 + (q >> 1)*8 + (q & 1);
                    As[base + 0] = __uint_as_float(f2tf(v.x));
                    As[base + 2] = __uint_as_float(f2tf(v.y));
                    As[base + 4] = __uint_as_float(f2tf(v.z));
                    As[base + 6] = __uint_as_float(f2tf(v.w));
                }
                // B tile: straight copy of pre-permuted tf32 weights
                {
                    const uint32_t* src = g_Wt + (size_t)j*65536 + c*32;
                    #pragma unroll
                    for (int r = 0; r < 4; r++) {
                        int e = r*256 + tid;
                        int n = e >> 3, q = e & 7;
                        float4 v = *(const float4*)(src + (size_t)n*512 + q*4);
                        *(float4*)&Bt[n*36 + q*4] = v;
                    }
                }
                __syncthreads();
                #pragma unroll
                for (int ks = 0; ks < 4; ks++) {
                    uint32_t a[2][4], bb[8][2];
                    #pragma unroll
                    for (int mi = 0; mi < 2; mi++) {
                        int row = warpM + mi*16 + qr;
                        float2 t0 = *(const float2*)&As[row*36 + ks*8 + qc*2];
                        float2 t1 = *(const float2*)&As[(row + 8)*36 + ks*8 + qc*2];
                        a[mi][0] = __float_as_uint(t0.x); a[mi][1] = __float_as_uint(t1.x);
                        a[mi][2] = __float_as_uint(t0.y); a[mi][3] = __float_as_uint(t1.y);
                    }
                    #pragma unroll
                    for (int ni = 0; ni < 8; ni++) {
                        int coln = warpN + ni*8 + qr;
                        float2 t = *(const float2*)&Bt[coln*36 + ks*8 + qc*2];
                        bb[ni][0] = __float_as_uint(t.x); bb[ni][1] = __float_as_uint(t.y);
                    }
                    #pragma unroll
                    for (int mi = 0; mi < 2; mi++)
                        #pragma unroll
                        for (int ni = 0; ni < 8; ni++)
                            mma_tf32(acc[mi][ni], a[mi], bb[ni]);
                }
            }
            __syncthreads();
            // init per-row projection accumulators with bias (all 512 entries)
            {
                float bv = SB[j*4 + (tid & 3)];
                PRJ[tid]       = bv;
                PRJ[tid + 256] = bv;
            }
            __syncthreads();

            // epilogue: adds + ReLU + partial [*,4] projection, in registers
            #pragma unroll
            for (int mi = 0; mi < 2; mi++) {
                #pragma unroll
                for (int h = 0; h < 2; h++) {
                    int r = warpM + mi*16 + qr + h*8;
                    int lT = lbl[r], lH = lbl[128 + r], lS = lbl[256 + r];
                    float p0 = 0.f, p1 = 0.f, p2 = 0.f, p3 = 0.f;
                    #pragma unroll
                    for (int ni = 0; ni < 8; ni++) {
                        int col = warpN + ni*8 + qc*2;
                        float v0 = acc[mi][ni][h*2], v1 = acc[mi][ni][h*2 + 1];
                        float add0, add1;
                        if (j == 0) {
                            float2 t = *(const float2*)&g_tables[0][lT][col];
                            add0 = t.x; add1 = t.y;
                        } else if (j == 1) {
                            float2 t1 = *(const float2*)&g_tables[1][lH][col];
                            float2 t2 = *(const float2*)&g_tables[2][lT][col];
                            add0 = PG[col] + t1.x + t2.x;
                            add1 = PG[col + 1] + t1.y + t2.y;
                        } else {
                            float2 t1 = *(const float2*)&g_tables[3][lS][col];
                            float2 t2 = *(const float2*)&g_tables[4][lT][col];
                            add0 = PG[128 + col] + t1.x + t2.x;
                            add1 = PG[128 + col + 1] + t1.y + t2.y;
                        }
                        float H0 = fmaxf(v0 + add0, 0.f);
                        float H1 = fmaxf(v1 + add1, 0.f);
                        const float* w = SW + j*512 + col*4;
                        p0 += H0*w[0] + H1*w[4];
                        p1 += H0*w[1] + H1*w[5];
                        p2 += H0*w[2] + H1*w[6];
                        p3 += H0*w[3] + H1*w[7];
                    }
                    p0 += __shfl_xor_sync(0xffffffffu, p0, 1);
                    p0 += __shfl_xor_sync(0xffffffffu, p0, 2);
                    p1 += __shfl_xor_sync(0xffffffffu, p1, 1);
                    p1 += __shfl_xor_sync(0xffffffffu, p1, 2);
                    p2 += __shfl_xor_sync(0xffffffffu, p2, 1);
                    p2 += __shfl_xor_sync(0xffffffffu, p2, 2);
                    p3 += __shfl_xor_sync(0xffffffffu, p3, 1);
                    p3 += __shfl_xor_sync(0xffffffffu, p3, 2);
                    float pl = (qc == 0) ? p0 : ((qc == 1) ? p1 : ((qc == 2) ? p2 : p3));
                    atomicAdd(&PRJ[r*4 + qc], pl);
                }
            }
            __syncthreads();
            if (tid < 128) {
                int m = tid;
                float g0 = 1.f/(1.f + expf(-PRJ[m*4 + 0]));
                float g1 = 1.f/(1.f + expf(-PRJ[m*4 + 1]));
                float g2 = 1.f/(1.f + expf(-PRJ[m*4 + 2]));
                float g3 = 1.f/(1.f + expf(-PRJ[m*4 + 3]));
                if (j == 1) {
                    const float* hsv = head_sister + (size_t)(rowbase + m)*4;
                    g0 *= hsv[0]; g1 *= hsv[1]; g2 *= hsv[2]; g3 *= hsv[3];
                } else if (j == 2) {
                    const float* tsv = tail_sister + (size_t)(rowbase + m)*4;
                    g0 *= tsv[0]; g1 *= tsv[1]; g2 *= tsv[2]; g3 *= tsv[3];
                }
                float* wp = Wsm + (size_t)(j*128 + m)*4;
                wp[0] = g0; wp[1] = g1; wp[2] = g2; wp[3] = g3;
            }
            __syncthreads();
        }

        // weighted segment sums for this tile
        {
            int c0 = tid, c1 = tid + 256;
            int l0 = tid >> 7, l1 = l0 + 2;
            float s00=0,s01=0,s02=0, s10=0,s11=0,s12=0;
            for (int n = 0; n < 128; n++) {
                float v0 = flat[(size_t)(rowbase + n)*512 + c0];
                float v1 = flat[(size_t)(rowbase + n)*512 + c1];
                float w0 = Wsm[(0*128+n)*4 + l0], w1 = Wsm[(1*128+n)*4 + l0], w2 = Wsm[(2*128+n)*4 + l0];
                float x0 = Wsm[(0*128+n)*4 + l1], x1 = Wsm[(1*128+n)*4 + l1], x2 = Wsm[(2*128+n)*4 + l1];
                s00 += w0*v0; s01 += w1*v0; s02 += w2*v0;
                s10 += x0*v1; s11 += x1*v1; s12 += x2*v1;
            }
            NUM[0*512 + c0] += s00; NUM[1*512 + c0] += s01; NUM[2*512 + c0] += s02;
            NUM[0*512 + c1] += s10; NUM[1*512 + c1] += s11; NUM[2*512 + c1] += s12;
            if (tid < 12) {
                int p = tid >> 2, l = tid & 3;
                float s = 0.f;
                for (int n = 0; n < 128; n++) s += Wsm[(p*128 + n)*4 + l];
                DEN[tid] += s;
            }
        }
        __syncthreads();
    }

    {
        int c0 = tid, c1 = tid + 256;
        int l0 = tid >> 7, l1 = l0 + 2;
        #pragma unroll
        for (int p = 0; p < 3; p++) {
            g_gsum[b][p][c0] = NUM[p*512 + c0] / DEN[p*4 + l0];
            g_gsum[b][p][c1] = NUM[p*512 + c1] / DEN[p*4 + l1];
        }
    }
}

// ---------------- kernel 3.5: assemble g_ht rows ------------------------
__global__ void k_ght(const float* __restrict__ flat,
                      const int* __restrict__ head_ids, const int* __restrict__ tail_ids,
                      const int* __restrict__ rel_labels,
                      const float* __restrict__ she, const float* __restrict__ ste)
{
    int b = blockIdx.x, tid = threadIdx.x;
    int h = head_ids[b], t = tail_ids[b];
    float* out = g_ght[b];
    for (int c = tid; c < 512; c += 256) {
        float ghs = g_gsum[b][1][c], gts = g_gsum[b][2][c];
        float hv = flat[(size_t)h*512 + c], tv = flat[(size_t)t*512 + c];
        out[c]        = ghs * hv;
        out[512 + c]  = gts * tv;
        out[1024 + c] = ghs;
        out[1536 + c] = gts;
        out[2048 + c] = hv;
        out[2560 + c] = tv;
    }
    if (tid < 64) {
        int r = rel_labels[b];
        out[3072 + tid] = she[r*64 + tid];
        out[3136 + tid] = ste[r*64 + tid];
    }
}

// ---------------- kernel 4a: ht GEMM split-K (partials) -----------------
__global__ __launch_bounds__(256) void k_ht(const float* __restrict__ ht_w)
{
    __shared__ float As2[64][33], Bs2[32][65];
    int m0 = blockIdx.y*64, n0 = blockIdx.x*64, kbase = blockIdx.z*800;
    int tid = threadIdx.x, tx = tid & 15, ty = tid >> 4;
    float acc[4][4] = {};
    for (int kc = 0; kc < 25; kc++) {
        int k0 = kbase + kc*32;
        #pragma unroll
        for (int r = 0; r < 8; r++) {
            int e = r*256 + tid; int m = e >> 5, k = e & 31;
            As2[m][k] = g_ght[m0 + m][k0 + k];
        }
        #pragma unroll
        for (int r = 0; r < 8; r++) {
            int e = r*256 + tid; int k = e >> 6, n = e & 63;
            Bs2[k][n] = ht_w[(size_t)(k0 + k)*512 + n0 + n];
        }
        __syncthreads();
        #pragma unroll
        for (int k = 0; k < 32; k++) {
            float a[4], bv[4];
            #pragma unroll
            for (int i = 0; i < 4; i++) { a[i] = As2[ty*4 + i][k]; bv[i] = Bs2[k][tx*4 + i]; }
            #pragma unroll
            for (int i = 0; i < 4; i++)
                #pragma unroll
                for (int q = 0; q < 4; q++) acc[i][q] += a[i]*bv[q];
        }
        __syncthreads();
    }
    #pragma unroll
    for (int i = 0; i < 4; i++)
        #pragma unroll
        for (int q = 0; q < 4; q++)
            g_htacc[blockIdx.z][m0 + ty*4 + i][n0 + tx*4 + q] = acc[i][q];
}

// ---------------- kernel 4b: fc + out -----------------------------------
__global__ void k_final(const float* __restrict__ flat,
                        const int* __restrict__ head_ids, const int* __restrict__ tail_ids,
                        const int* __restrict__ rel_labels, const float* __restrict__ rel_emb,
                        const float* __restrict__ ht_b,
                        const float* __restrict__ fc_w, const float* __restrict__ fc_b,
                        const float* __restrict__ out_w, const float* __restrict__ out_b,
                        float* __restrict__ out)
{
    __shared__ float rep[2112];
    __shared__ float red[256][17];
    int b = blockIdx.x, tid = threadIdx.x;
    int h = head_ids[b], t = tail_ids[b];
    for (int c = tid; c < 512; c += 256) {
        rep[c]        = g_gsum[b][0][c];
        rep[512 + c]  = flat[(size_t)h*512 + c];
        rep[1024 + c] = flat[(size_t)t*512 + c];
        float s = g_htacc[0][b][c] + g_htacc[1][b][c] + g_htacc[2][b][c] + g_htacc[3][b][c];
        rep[1536 + c] = fmaxf(s + ht_b[c], 0.f);
    }
    if (tid < 64) rep[2048 + tid] = rel_emb[rel_labels[b]*64 + tid];
    __syncthreads();

    float acc[16];
    #pragma unroll
    for (int j = 0; j < 16; j++) acc[j] = 0.f;
    for (int k = tid; k < 2112; k += 256) {
        float x = rep[k];
        const float4* w = (const float4*)(fc_w + (size_t)k*16);
        #pragma unroll
        for (int v = 0; v < 4; v++) {
            float4 ww = w[v];
            acc[v*4+0] += x*ww.x; acc[v*4+1] += x*ww.y;
            acc[v*4+2] += x*ww.z; acc[v*4+3] += x*ww.w;
        }
    }
    #pragma unroll
    for (int j = 0; j < 16; j++) red[tid][j] = acc[j];
    __syncthreads();
    for (int s = 128; s >= 1; s >>= 1) {
        if (tid < s) {
            #pragma unroll
            for (int j = 0; j < 16; j++) red[tid][j] += red[tid + s][j];
        }
        __syncthreads();
    }
    if (tid == 0) {
        float o = out_b[0];
        #pragma unroll
        for (int j = 0; j < 16; j++) o += fmaxf(red[0][j] + fc_b[j], 0.f) * out_w[j];
        out[b] = o;
    }
}

// ---------------- launch ------------------------------------------------
extern "C" void kernel_launch(void* const* d_in, const int* in_sizes, int n_in,
                              void* d_out, int out_size)
{
    const float* node_repr = (const float*)d_in[0];
    const float* head_sis  = (const float*)d_in[1];
    const float* tail_sis  = (const float*)d_in[2];
    const int*   t_label   = (const int*)d_in[3];
    const int*   hstp      = (const int*)d_in[4];
    const int*   tstp      = (const int*)d_in[5];
    const int*   head_ids  = (const int*)d_in[7];
    const int*   tail_ids  = (const int*)d_in[8];
    const int*   rel_lab   = (const int*)d_in[9];
    const float* rel_emb   = (const float*)d_in[10];
    const float* she       = (const float*)d_in[11];
    const float* ste       = (const float*)d_in[12];
    const float* A_w  = (const float*)d_in[13]; const float* A_b  = (const float*)d_in[14];
    const float* B_w  = (const float*)d_in[15]; const float* B_b  = (const float*)d_in[16];
    const float* C_w  = (const float*)d_in[17]; const float* C_b  = (const float*)d_in[18];
    const float* Dm_w = (const float*)d_in[19]; const float* Dm_b = (const float*)d_in[20];
    const float* E_w  = (const float*)d_in[21]; const float* E_b  = (const float*)d_in[22];
    const float* G_w  = (const float*)d_in[23]; const float* G_b  = (const float*)d_in[24];
    const float* ht_w = (const float*)d_in[25]; const float* ht_b = (const float*)d_in[26];
    const float* fc_w = (const float*)d_in[27]; const float* fc_b = (const float*)d_in[28];
    const float* out_w= (const float*)d_in[29]; const float* out_b= (const float*)d_in[30];
    float* out = (float*)d_out;

    const int smemBytes = SM_FLOATS * 4;
    cudaFuncSetAttribute(k_fused_mma, cudaFuncAttributeMaxDynamicSharedMemorySize, smemBytes);

    k_tables<<<dim3(Rr, 5), 128>>>(rel_emb, she, ste, A_w, A_b, C_w, C_b, E_w, E_b);
    k_prep<<<dim3(16, 3), 256>>>(A_w, C_w, E_w);
    k_pg<<<dim3(4, 16, 2), 256>>>(node_repr, head_ids, tail_ids, C_w, E_w);
    k_fused_mma<<<Bg, 256, smemBytes>>>(node_repr, head_sis, tail_sis, t_label, hstp, tstp,
                                        B_w, B_b, Dm_w, Dm_b, G_w, G_b);
    k_ght<<<Bg, 256>>>(node_repr, head_ids, tail_ids, rel_lab, she, ste);
    k_ht<<<dim3(8, 8, 4), 256>>>(ht_w);
    k_final<<<Bg, 256>>>(node_repr, head_ids, tail_ids, rel_lab, rel_emb, ht_b,
                         fc_w, fc_b, out_w, out_b, out);
}

// round 8
// speedup vs baseline: 2.3236x; 1.3012x over previous
#include <cuda_runtime.h>
#include <math.h>
#include <stdint.h>

#define Bg   512
#define NPG  256
#define Rr   51

// ---------------- device scratch ----------------
__device__ float g_tables[5][Rr][128];
__device__ float g_PG[2][Bg][128];
__device__ float g_gsum[Bg][3][512];
__device__ float g_ght[Bg][3200];
__device__ float g_htacc[4][Bg][512];
__device__ uint4 g_Wt[3 * 16 * 512];       // [j][chunk][nb*32 + g*4 + t] b-frag quads (both s)
__device__ uint4 g_A[8192u * 32u * 32u];   // [G][s][g*4+t] a-frag quads (128 MB)

__device__ __forceinline__ uint32_t packbf(float lo, float hi) {
    uint32_t p;
    asm("cvt.rn.bf16x2.f32 %0, %1, %2;" : "=r"(p) : "f"(hi), "f"(lo));
    return p;
}
__device__ __forceinline__ void mma_bf16(float* d, const uint32_t* a, uint32_t b0, uint32_t b1) {
    asm volatile(
        "mma.sync.aligned.m16n8k16.row.col.f32.bf16.bf16.f32 "
        "{%0,%1,%2,%3}, {%4,%5,%6,%7}, {%8,%9}, {%0,%1,%2,%3};"
        : "+f"(d[0]), "+f"(d[1]), "+f"(d[2]), "+f"(d[3])
        : "r"(a[0]), "r"(a[1]), "r"(a[2]), "r"(a[3]), "r"(b0), "r"(b1));
}

// ---------------- kernel 1: label tables -------------------------------
__global__ void k_tables(const float* __restrict__ rel_emb,
                         const float* __restrict__ she,
                         const float* __restrict__ ste,
                         const float* __restrict__ A_w, const float* __restrict__ A_b,
                         const float* __restrict__ C_w, const float* __restrict__ C_b,
                         const float* __restrict__ E_w, const float* __restrict__ E_b)
{
    int r = blockIdx.x, t = blockIdx.y, d = threadIdx.x;
    const float* emb; const float* W; const float* bias = 0;
    switch (t) {
        case 0: emb = rel_emb; W = A_w + 512*128;  bias = A_b; break;
        case 1: emb = she;     W = C_w + 1536*128;             break;
        case 2: emb = she;     W = C_w + 1600*128; bias = C_b; break;
        case 3: emb = ste;     W = E_w + 1536*128;             break;
        default:emb = ste;     W = E_w + 1600*128; bias = E_b; break;
    }
    float acc = bias ? bias[d] : 0.f;
    for (int k = 0; k < 64; k++) acc += emb[r*64 + k] * W[k*128 + d];
    g_tables[t][r][d] = acc;
}

// ---------------- kernel 1b: bake bf16 weight fragments -----------------
__global__ void k_prep(const float* __restrict__ A_w, const float* __restrict__ C_w,
                       const float* __restrict__ E_w)
{
    int c = blockIdx.x;   // chunk 0..15 (32 k)
    int j = blockIdx.y;   // path 0..2
    const float* W = (j == 0) ? A_w : ((j == 1) ? C_w : E_w);
    uint4* dst = g_Wt + (size_t)(j*16 + c)*512;
    for (int r = 0; r < 2; r++) {
        int q = r*256 + threadIdx.x;         // 0..511
        int nb = q >> 5, idx = q & 31;
        int g = idx >> 2, t = idx & 3;
        int n = nb*8 + g;
        int k00 = c*32 + 2*t;
        uint4 v;
        v.x = packbf(W[(size_t)(k00 +  0)*128 + n], W[(size_t)(k00 +  1)*128 + n]);
        v.y = packbf(W[(size_t)(k00 +  8)*128 + n], W[(size_t)(k00 +  9)*128 + n]);
        v.z = packbf(W[(size_t)(k00 + 16)*128 + n], W[(size_t)(k00 + 17)*128 + n]);
        v.w = packbf(W[(size_t)(k00 + 24)*128 + n], W[(size_t)(k00 + 25)*128 + n]);
        dst[q] = v;
    }
}

// ---------------- kernel 1c: stage A as bf16 fragment quads -------------
__global__ void k_aprep(const float* __restrict__ flat)
{
    int G = blockIdx.x;            // 16-row group 0..8191
    #pragma unroll
    for (int r = 0; r < 4; r++) {
        int q = r*256 + threadIdx.x;   // 0..1023 = [s 0..31][idx 0..31]
        int s = q >> 5, idx = q & 31;
        int g = idx >> 2, tt = idx & 3;
        size_t r0 = (size_t)G*16 + g, r1 = r0 + 8;
        int k0 = s*16 + 2*tt;
        float2 x  = *(const float2*)(flat + r0*512 + k0);
        float2 y  = *(const float2*)(flat + r1*512 + k0);
        float2 x8 = *(const float2*)(flat + r0*512 + k0 + 8);
        float2 y8 = *(const float2*)(flat + r1*512 + k0 + 8);
        uint4 v;
        v.x = packbf(x.x,  x.y);
        v.y = packbf(y.x,  y.y);
        v.z = packbf(x8.x, x8.y);
        v.w = packbf(y8.x, y8.y);
        g_A[((size_t)G*32 + s)*32 + idx] = v;
    }
}

// ---------------- kernel 2: per-graph PG terms --------------------------
__global__ void k_pg(const float* __restrict__ flat,
                     const int* __restrict__ head_ids, const int* __restrict__ tail_ids,
                     const float* __restrict__ C_w, const float* __restrict__ E_w)
{
    int path = blockIdx.z;
    const float* W = (path == 0 ? C_w : E_w) + 512*128;
    int m0 = blockIdx.y * 32, n0 = blockIdx.x * 32;
    __shared__ float As[32][33], Bs[32][33];
    __shared__ int rowA[32], rowB[32];
    int tid = threadIdx.x;
    if (tid < 32) {
        int g = m0 + tid;
        int h = head_ids[g], t = tail_ids[g];
        rowA[tid] = (path == 0) ? h : t;
        rowB[tid] = (path == 0) ? t : h;
    }
    __syncthreads();
    int tx = tid & 15, ty = tid >> 4;
    float acc[2][2] = {{0.f,0.f},{0.f,0.f}};
    for (int k0 = 0; k0 < 1024; k0 += 32) {
        for (int e = tid; e < 1024; e += 256) {
            int m = e >> 5, k = e & 31;
            int kg = k0 + k;
            int row = (kg < 512) ? rowA[m] : rowB[m];
            int kk  = (kg < 512) ? kg : kg - 512;
            As[m][k] = flat[(size_t)row*512 + kk];
        }
        for (int e = tid; e < 1024; e += 256) {
            int k = e >> 5, n = e & 31;
            Bs[k][n] = W[(size_t)(k0 + k)*128 + n0 + n];
        }
        __syncthreads();
        #pragma unroll
        for (int k = 0; k < 32; k++) {
            float a0 = As[ty*2][k], a1 = As[ty*2+1][k];
            float b0 = Bs[k][tx*2], b1 = Bs[k][tx*2+1];
            acc[0][0] += a0*b0; acc[0][1] += a0*b1;
            acc[1][0] += a1*b0; acc[1][1] += a1*b1;
        }
        __syncthreads();
    }
    #pragma unroll
    for (int i = 0; i < 2; i++)
        #pragma unroll
        for (int q = 0; q < 2; q++)
            g_PG[path][m0 + ty*2 + i][n0 + tx*2 + q] = acc[i][q];
}

// ---------------- kernel 3: fused pipeline (bf16 m16n8k16) --------------
// smem float offsets
#define AS_OFF   0        // 512 uint4 = 2048 f
#define BT_OFF   2048     // 512 uint4 = 2048 f
#define SW_OFF   4096     // 1536
#define SB_OFF   5632     // 16
#define PG_OFF   5648     // 256
#define WSM_OFF  5904     // 1536
#define NUM_OFF  7440     // 1536
#define DEN_OFF  8976     // 16
#define PRJ_OFF  8992     // 512
#define LBL_OFF  9504     // 384 ints
#define SM_FLOATS 9888

__global__ __launch_bounds__(256, 2) void k_fused_mma(
    const float* __restrict__ flat,
    const float* __restrict__ head_sister, const float* __restrict__ tail_sister,
    const int* __restrict__ t_label, const int* __restrict__ hst, const int* __restrict__ tst,
    const float* __restrict__ B_w, const float* __restrict__ B_b,
    const float* __restrict__ Dm_w, const float* __restrict__ Dm_b,
    const float* __restrict__ G_w, const float* __restrict__ G_b)
{
    extern __shared__ float sm[];
    uint4* AsU  = (uint4*)(sm + AS_OFF);
    uint4* BtU  = (uint4*)(sm + BT_OFF);
    float* SW   = sm + SW_OFF;
    float* SB   = sm + SB_OFF;
    float* PG   = sm + PG_OFF;
    float* Wsm  = sm + WSM_OFF;
    float* NUM  = sm + NUM_OFF;
    float* DEN  = sm + DEN_OFF;
    float* PRJ  = sm + PRJ_OFF;
    int*   lbl  = (int*)(sm + LBL_OFF);

    const int b    = blockIdx.x;
    const int tid  = threadIdx.x;
    const int lane = tid & 31;
    const int wid  = tid >> 5;
    const int warpM = (wid & 3) * 32;
    const int warpN = (wid >> 2) * 64;
    const int qr = lane >> 2;
    const int qc = lane & 3;
    const int GlocBase = (wid & 3) * 2;        // warpM/16
    const int nbBase   = (wid >> 2) * 8;       // warpN/8

    for (int i = tid; i < 512; i += 256) {
        SW[i] = B_w[i]; SW[512 + i] = Dm_w[i]; SW[1024 + i] = G_w[i];
    }
    if (tid < 12) {
        int p = tid >> 2, l = tid & 3;
        SB[tid] = (p == 0) ? B_b[l] : ((p == 1) ? Dm_b[l] : G_b[l]);
        DEN[tid] = 0.f;
    }
    PG[tid] = g_PG[tid >> 7][b][tid & 127];
    for (int i = tid; i < 1536; i += 256) NUM[i] = 0.f;
    __syncthreads();

    for (int mt = 0; mt < 2; mt++) {
        const int rowbase = b*NPG + mt*128;
        const int Gbase = rowbase >> 4;
        if (tid < 128) {
            lbl[tid]       = t_label[rowbase + tid];
            lbl[128 + tid] = hst[rowbase + tid];
            lbl[256 + tid] = tst[rowbase + tid];
        }
        __syncthreads();

        for (int j = 0; j < 3; j++) {
            float acc[2][8][4];
            #pragma unroll
            for (int mi = 0; mi < 2; mi++)
                #pragma unroll
                for (int ni = 0; ni < 8; ni++)
                    #pragma unroll
                    for (int q = 0; q < 4; q++) acc[mi][ni][q] = 0.f;

            const uint4* srcBbase = g_Wt + (size_t)j*16*512;

            for (int c = 0; c < 16; c++) {
                __syncthreads();
                // A fill: straight quad copy from staged gmem
                #pragma unroll
                for (int r = 0; r < 2; r++) {
                    int q = r*256 + tid;
                    int Gl = q >> 6, rem = q & 63;
                    int sl = rem >> 5, idx = rem & 31;
                    AsU[q] = g_A[((size_t)(Gbase + Gl)*32 + 2*c + sl)*32 + idx];
                }
                // B fill: straight quad copy
                {
                    const uint4* srcB = srcBbase + (size_t)c*512;
                    #pragma unroll
                    for (int r = 0; r < 2; r++)
                        BtU[r*256 + tid] = srcB[r*256 + tid];
                }
                __syncthreads();

                uint4 bv[8];
                #pragma unroll
                for (int ni = 0; ni < 8; ni++)
                    bv[ni] = BtU[(nbBase + ni)*32 + qr*4 + qc];
                #pragma unroll
                for (int s = 0; s < 2; s++) {
                    #pragma unroll
                    for (int mi = 0; mi < 2; mi++) {
                        uint4 av = AsU[(GlocBase + mi)*64 + s*32 + qr*4 + qc];
                        uint32_t a[4] = {av.x, av.y, av.z, av.w};
                        #pragma unroll
                        for (int ni = 0; ni < 8; ni++) {
                            uint32_t b0 = s ? bv[ni].z : bv[ni].x;
                            uint32_t b1 = s ? bv[ni].w : bv[ni].y;
                            mma_bf16(acc[mi][ni], a, b0, b1);
                        }
                    }
                }
            }
            __syncthreads();
            // init per-row projection accumulators with bias (all 512 entries)
            {
                float bvv = SB[j*4 + (tid & 3)];
                PRJ[tid]       = bvv;
                PRJ[tid + 256] = bvv;
            }
            __syncthreads();

            // epilogue: adds + ReLU + partial [*,4] projection, in registers
            #pragma unroll
            for (int mi = 0; mi < 2; mi++) {
                #pragma unroll
                for (int h = 0; h < 2; h++) {
                    int r = warpM + mi*16 + qr + h*8;
                    int lT = lbl[r], lH = lbl[128 + r], lS = lbl[256 + r];
                    float p0 = 0.f, p1 = 0.f, p2 = 0.f, p3 = 0.f;
                    #pragma unroll
                    for (int ni = 0; ni < 8; ni++) {
                        int col = warpN + ni*8 + qc*2;
                        float v0 = acc[mi][ni][h*2], v1 = acc[mi][ni][h*2 + 1];
                        float add0, add1;
                        if (j == 0) {
                            float2 t = *(const float2*)&g_tables[0][lT][col];
                            add0 = t.x; add1 = t.y;
                        } else if (j == 1) {
                            float2 t1 = *(const float2*)&g_tables[1][lH][col];
                            float2 t2 = *(const float2*)&g_tables[2][lT][col];
                            add0 = PG[col] + t1.x + t2.x;
                            add1 = PG[col + 1] + t1.y + t2.y;
                        } else {
                            float2 t1 = *(const float2*)&g_tables[3][lS][col];
                            float2 t2 = *(const float2*)&g_tables[4][lT][col];
                            add0 = PG[128 + col] + t1.x + t2.x;
                            add1 = PG[128 + col + 1] + t1.y + t2.y;
                        }
                        float H0 = fmaxf(v0 + add0, 0.f);
                        float H1 = fmaxf(v1 + add1, 0.f);
                        const float* w = SW + j*512 + col*4;
                        p0 += H0*w[0] + H1*w[4];
                        p1 += H0*w[1] + H1*w[5];
                        p2 += H0*w[2] + H1*w[6];
                        p3 += H0*w[3] + H1*w[7];
                    }
                    p0 += __shfl_xor_sync(0xffffffffu, p0, 1);
                    p0 += __shfl_xor_sync(0xffffffffu, p0, 2);
                    p1 += __shfl_xor_sync(0xffffffffu, p1, 1);
                    p1 += __shfl_xor_sync(0xffffffffu, p1, 2);
                    p2 += __shfl_xor_sync(0xffffffffu, p2, 1);
                    p2 += __shfl_xor_sync(0xffffffffu, p2, 2);
                    p3 += __shfl_xor_sync(0xffffffffu, p3, 1);
                    p3 += __shfl_xor_sync(0xffffffffu, p3, 2);
                    float pl = (qc == 0) ? p0 : ((qc == 1) ? p1 : ((qc == 2) ? p2 : p3));
                    atomicAdd(&PRJ[r*4 + qc], pl);
                }
            }
            __syncthreads();
            if (tid < 128) {
                int m = tid;
                float g0 = 1.f/(1.f + expf(-PRJ[m*4 + 0]));
                float g1 = 1.f/(1.f + expf(-PRJ[m*4 + 1]));
                float g2 = 1.f/(1.f + expf(-PRJ[m*4 + 2]));
                float g3 = 1.f/(1.f + expf(-PRJ[m*4 + 3]));
                if (j == 1) {
                    const float* hsv = head_sister + (size_t)(rowbase + m)*4;
                    g0 *= hsv[0]; g1 *= hsv[1]; g2 *= hsv[2]; g3 *= hsv[3];
                } else if (j == 2) {
                    const float* tsv = tail_sister + (size_t)(rowbase + m)*4;
                    g0 *= tsv[0]; g1 *= tsv[1]; g2 *= tsv[2]; g3 *= tsv[3];
                }
                float* wp = Wsm + (size_t)(j*128 + m)*4;
                wp[0] = g0; wp[1] = g1; wp[2] = g2; wp[3] = g3;
            }
            __syncthreads();
        }

        // weighted segment sums for this tile
        {
            int c0 = tid, c1 = tid + 256;
            int l0 = tid >> 7, l1 = l0 + 2;
            float s00=0,s01=0,s02=0, s10=0,s11=0,s12=0;
            for (int n = 0; n < 128; n++) {
                float v0 = flat[(size_t)(rowbase + n)*512 + c0];
                float v1 = flat[(size_t)(rowbase + n)*512 + c1];
                float w0 = Wsm[(0*128+n)*4 + l0], w1 = Wsm[(1*128+n)*4 + l0], w2 = Wsm[(2*128+n)*4 + l0];
                float x0 = Wsm[(0*128+n)*4 + l1], x1 = Wsm[(1*128+n)*4 + l1], x2 = Wsm[(2*128+n)*4 + l1];
                s00 += w0*v0; s01 += w1*v0; s02 += w2*v0;
                s10 += x0*v1; s11 += x1*v1; s12 += x2*v1;
            }
            NUM[0*512 + c0] += s00; NUM[1*512 + c0] += s01; NUM[2*512 + c0] += s02;
            NUM[0*512 + c1] += s10; NUM[1*512 + c1] += s11; NUM[2*512 + c1] += s12;
            if (tid < 12) {
                int p = tid >> 2, l = tid & 3;
                float s = 0.f;
                for (int n = 0; n < 128; n++) s += Wsm[(p*128 + n)*4 + l];
                DEN[tid] += s;
            }
        }
        __syncthreads();
    }

    {
        int c0 = tid, c1 = tid + 256;
        int l0 = tid >> 7, l1 = l0 + 2;
        #pragma unroll
        for (int p = 0; p < 3; p++) {
            g_gsum[b][p][c0] = NUM[p*512 + c0] / DEN[p*4 + l0];
            g_gsum[b][p][c1] = NUM[p*512 + c1] / DEN[p*4 + l1];
        }
    }
}

// ---------------- kernel 3.5: assemble g_ht rows ------------------------
__global__ void k_ght(const float* __restrict__ flat,
                      const int* __restrict__ head_ids, const int* __restrict__ tail_ids,
                      const int* __restrict__ rel_labels,
                      const float* __restrict__ she, const float* __restrict__ ste)
{
    int b = blockIdx.x, tid = threadIdx.x;
    int h = head_ids[b], t = tail_ids[b];
    float* out = g_ght[b];
    for (int c = tid; c < 512; c += 256) {
        float ghs = g_gsum[b][1][c], gts = g_gsum[b][2][c];
        float hv = flat[(size_t)h*512 + c], tv = flat[(size_t)t*512 + c];
        out[c]        = ghs * hv;
        out[512 + c]  = gts * tv;
        out[1024 + c] = ghs;
        out[1536 + c] = gts;
        out[2048 + c] = hv;
        out[2560 + c] = tv;
    }
    if (tid < 64) {
        int r = rel_labels[b];
        out[3072 + tid] = she[r*64 + tid];
        out[3136 + tid] = ste[r*64 + tid];
    }
}

// ---------------- kernel 4a: ht GEMM split-K (partials) -----------------
__global__ __launch_bounds__(256) void k_ht(const float* __restrict__ ht_w)
{
    __shared__ float As2[64][33], Bs2[32][65];
    int m0 = blockIdx.y*64, n0 = blockIdx.x*64, kbase = blockIdx.z*800;
    int tid = threadIdx.x, tx = tid & 15, ty = tid >> 4;
    float acc[4][4] = {};
    for (int kc = 0; kc < 25; kc++) {
        int k0 = kbase + kc*32;
        #pragma unroll
        for (int r = 0; r < 8; r++) {
            int e = r*256 + tid; int m = e >> 5, k = e & 31;
            As2[m][k] = g_ght[m0 + m][k0 + k];
        }
        #pragma unroll
        for (int r = 0; r < 8; r++) {
            int e = r*256 + tid; int k = e >> 6, n = e & 63;
            Bs2[k][n] = ht_w[(size_t)(k0 + k)*512 + n0 + n];
        }
        __syncthreads();
        #pragma unroll
        for (int k = 0; k < 32; k++) {
            float a[4], bv[4];
            #pragma unroll
            for (int i = 0; i < 4; i++) { a[i] = As2[ty*4 + i][k]; bv[i] = Bs2[k][tx*4 + i]; }
            #pragma unroll
            for (int i = 0; i < 4; i++)
                #pragma unroll
                for (int q = 0; q < 4; q++) acc[i][q] += a[i]*bv[q];
        }
        __syncthreads();
    }
    #pragma unroll
    for (int i = 0; i < 4; i++)
        #pragma unroll
        for (int q = 0; q < 4; q++)
            g_htacc[blockIdx.z][m0 + ty*4 + i][n0 + tx*4 + q] = acc[i][q];
}

// ---------------- kernel 4b: fc + out -----------------------------------
__global__ void k_final(const float* __restrict__ flat,
                        const int* __restrict__ head_ids, const int* __restrict__ tail_ids,
                        const int* __restrict__ rel_labels, const float* __restrict__ rel_emb,
                        const float* __restrict__ ht_b,
                        const float* __restrict__ fc_w, const float* __restrict__ fc_b,
                        const float* __restrict__ out_w, const float* __restrict__ out_b,
                        float* __restrict__ out)
{
    __shared__ float rep[2112];
    __shared__ float red[256][17];
    int b = blockIdx.x, tid = threadIdx.x;
    int h = head_ids[b], t = tail_ids[b];
    for (int c = tid; c < 512; c += 256) {
        rep[c]        = g_gsum[b][0][c];
        rep[512 + c]  = flat[(size_t)h*512 + c];
        rep[1024 + c] = flat[(size_t)t*512 + c];
        float s = g_htacc[0][b][c] + g_htacc[1][b][c] + g_htacc[2][b][c] + g_htacc[3][b][c];
        rep[1536 + c] = fmaxf(s + ht_b[c], 0.f);
    }
    if (tid < 64) rep[2048 + tid] = rel_emb[rel_labels[b]*64 + tid];
    __syncthreads();

    float acc[16];
    #pragma unroll
    for (int j = 0; j < 16; j++) acc[j] = 0.f;
    for (int k = tid; k < 2112; k += 256) {
        float x = rep[k];
        const float4* w = (const float4*)(fc_w + (size_t)k*16);
        #pragma unroll
        for (int v = 0; v < 4; v++) {
            float4 ww = w[v];
            acc[v*4+0] += x*ww.x; acc[v*4+1] += x*ww.y;
            acc[v*4+2] += x*ww.z; acc[v*4+3] += x*ww.w;
        }
    }
    #pragma unroll
    for (int j = 0; j < 16; j++) red[tid][j] = acc[j];
    __syncthreads();
    for (int s = 128; s >= 1; s >>= 1) {
        if (tid < s) {
            #pragma unroll
            for (int j = 0; j < 16; j++) red[tid][j] += red[tid + s][j];
        }
        __syncthreads();
    }
    if (tid == 0) {
        float o = out_b[0];
        #pragma unroll
        for (int j = 0; j < 16; j++) o += fmaxf(red[0][j] + fc_b[j], 0.f) * out_w[j];
        out[b] = o;
    }
}

// ---------------- launch ------------------------------------------------
extern "C" void kernel_launch(void* const* d_in, const int* in_sizes, int n_in,
                              void* d_out, int out_size)
{
    const float* node_repr = (const float*)d_in[0];
    const float* head_sis  = (const float*)d_in[1];
    const float* tail_sis  = (const float*)d_in[2];
    const int*   t_label   = (const int*)d_in[3];
    const int*   hstp      = (const int*)d_in[4];
    const int*   tstp      = (const int*)d_in[5];
    const int*   head_ids  = (const int*)d_in[7];
    const int*   tail_ids  = (const int*)d_in[8];
    const int*   rel_lab   = (const int*)d_in[9];
    const float* rel_emb   = (const float*)d_in[10];
    const float* she       = (const float*)d_in[11];
    const float* ste       = (const float*)d_in[12];
    const float* A_w  = (const float*)d_in[13]; const float* A_b  = (const float*)d_in[14];
    const float* B_w  = (const float*)d_in[15]; const float* B_b  = (const float*)d_in[16];
    const float* C_w  = (const float*)d_in[17]; const float* C_b  = (const float*)d_in[18];
    const float* Dm_w = (const float*)d_in[19]; const float* Dm_b = (const float*)d_in[20];
    const float* E_w  = (const float*)d_in[21]; const float* E_b  = (const float*)d_in[22];
    const float* G_w  = (const float*)d_in[23]; const float* G_b  = (const float*)d_in[24];
    const float* ht_w = (const float*)d_in[25]; const float* ht_b = (const float*)d_in[26];
    const float* fc_w = (const float*)d_in[27]; const float* fc_b = (const float*)d_in[28];
    const float* out_w= (const float*)d_in[29]; const float* out_b= (const float*)d_in[30];
    float* out = (float*)d_out;

    const int smemBytes = SM_FLOATS * 4;
    cudaFuncSetAttribute(k_fused_mma, cudaFuncAttributeMaxDynamicSharedMemorySize, smemBytes);

    k_tables<<<dim3(Rr, 5), 128>>>(rel_emb, she, ste, A_w, A_b, C_w, C_b, E_w, E_b);
    k_prep<<<dim3(16, 3), 256>>>(A_w, C_w, E_w);
    k_aprep<<<8192, 256>>>(node_repr);
    k_pg<<<dim3(4, 16, 2), 256>>>(node_repr, head_ids, tail_ids, C_w, E_w);
    k_fused_mma<<<Bg, 256, smemBytes>>>(node_repr, head_sis, tail_sis, t_label, hstp, tstp,
                                        B_w, B_b, Dm_w, Dm_b, G_w, G_b);
    k_ght<<<Bg, 256>>>(node_repr, head_ids, tail_ids, rel_lab, she, ste);
    k_ht<<<dim3(8, 8, 4), 256>>>(ht_w);
    k_final<<<Bg, 256>>>(node_repr, head_ids, tail_ids, rel_lab, rel_emb, ht_b,
                         fc_w, fc_b, out_w, out_b, out);
}

// round 9
// speedup vs baseline: 2.8265x; 1.2164x over previous
#include <cuda_runtime.h>
#include <math.h>
#include <stdint.h>

#define Bg   512
#define NPG  256
#define Rr   51

// ---------------- device scratch ----------------
__device__ float g_tables[5][Rr][128];
__device__ float g_PGpart[8][2][Bg][128];
__device__ float g_gsum[Bg][3][512];
__device__ float g_ght[Bg][3200];
__device__ float g_htacc[10][Bg][512];
__device__ uint4 g_Wt[3 * 16 * 512];       // [j][chunk][nb*32 + lane] b-frag quads
__device__ uint4 g_A[8192u * 32u * 32u];   // [G][s][lane] a-frag quads (128 MB)

__device__ __forceinline__ uint32_t packbf(float lo, float hi) {
    uint32_t p;
    asm("cvt.rn.bf16x2.f32 %0, %1, %2;" : "=r"(p) : "f"(hi), "f"(lo));
    return p;
}
__device__ __forceinline__ void mma_bf16(float* d, const uint32_t* a, uint32_t b0, uint32_t b1) {
    asm volatile(
        "mma.sync.aligned.m16n8k16.row.col.f32.bf16.bf16.f32 "
        "{%0,%1,%2,%3}, {%4,%5,%6,%7}, {%8,%9}, {%0,%1,%2,%3};"
        : "+f"(d[0]), "+f"(d[1]), "+f"(d[2]), "+f"(d[3])
        : "r"(a[0]), "r"(a[1]), "r"(a[2]), "r"(a[3]), "r"(b0), "r"(b1));
}

// ---------------- kernel 1: label tables -------------------------------
__global__ void k_tables(const float* __restrict__ rel_emb,
                         const float* __restrict__ she,
                         const float* __restrict__ ste,
                         const float* __restrict__ A_w, const float* __restrict__ A_b,
                         const float* __restrict__ C_w, const float* __restrict__ C_b,
                         const float* __restrict__ E_w, const float* __restrict__ E_b)
{
    int r = blockIdx.x, t = blockIdx.y, d = threadIdx.x;
    const float* emb; const float* W; const float* bias = 0;
    switch (t) {
        case 0: emb = rel_emb; W = A_w + 512*128;  bias = A_b; break;
        case 1: emb = she;     W = C_w + 1536*128;             break;
        case 2: emb = she;     W = C_w + 1600*128; bias = C_b; break;
        case 3: emb = ste;     W = E_w + 1536*128;             break;
        default:emb = ste;     W = E_w + 1600*128; bias = E_b; break;
    }
    float acc = bias ? bias[d] : 0.f;
    for (int k = 0; k < 64; k++) acc += emb[r*64 + k] * W[k*128 + d];
    g_tables[t][r][d] = acc;
}

// ---------------- kernel 1b: bake bf16 weight fragments -----------------
__global__ void k_prep(const float* __restrict__ A_w, const float* __restrict__ C_w,
                       const float* __restrict__ E_w)
{
    int c = blockIdx.x;   // chunk 0..15 (32 k)
    int j = blockIdx.y;   // path 0..2
    const float* W = (j == 0) ? A_w : ((j == 1) ? C_w : E_w);
    uint4* dst = g_Wt + (size_t)(j*16 + c)*512;
    for (int r = 0; r < 2; r++) {
        int q = r*256 + threadIdx.x;         // 0..511
        int nb = q >> 5, idx = q & 31;
        int g = idx >> 2, t = idx & 3;
        int n = nb*8 + g;
        int k00 = c*32 + 2*t;
        uint4 v;
        v.x = packbf(W[(size_t)(k00 +  0)*128 + n], W[(size_t)(k00 +  1)*128 + n]);
        v.y = packbf(W[(size_t)(k00 +  8)*128 + n], W[(size_t)(k00 +  9)*128 + n]);
        v.z = packbf(W[(size_t)(k00 + 16)*128 + n], W[(size_t)(k00 + 17)*128 + n]);
        v.w = packbf(W[(size_t)(k00 + 24)*128 + n], W[(size_t)(k00 + 25)*128 + n]);
        dst[q] = v;
    }
}

// ---------------- kernel 1c: stage A as bf16 fragment quads -------------
__global__ void k_aprep(const float* __restrict__ flat)
{
    int G = blockIdx.x;            // 16-row group 0..8191
    #pragma unroll
    for (int r = 0; r < 4; r++) {
        int q = r*256 + threadIdx.x;   // 0..1023 = [s 0..31][idx 0..31]
        int s = q >> 5, idx = q & 31;
        int g = idx >> 2, tt = idx & 3;
        size_t r0 = (size_t)G*16 + g, r1 = r0 + 8;
        int k0 = s*16 + 2*tt;
        float2 x  = *(const float2*)(flat + r0*512 + k0);
        float2 y  = *(const float2*)(flat + r1*512 + k0);
        float2 x8 = *(const float2*)(flat + r0*512 + k0 + 8);
        float2 y8 = *(const float2*)(flat + r1*512 + k0 + 8);
        uint4 v;
        v.x = packbf(x.x,  x.y);
        v.y = packbf(y.x,  y.y);
        v.z = packbf(x8.x, x8.y);
        v.w = packbf(y8.x, y8.y);
        g_A[((size_t)G*32 + s)*32 + idx] = v;
    }
}

// ---------------- kernel 2: per-graph PG terms, split-K -----------------
// grid (16 mtile, 8 kslice, 2 path), 256 threads, 4x4 micro
__global__ __launch_bounds__(256) void k_pg(
    const float* __restrict__ flat,
    const int* __restrict__ head_ids, const int* __restrict__ tail_ids,
    const float* __restrict__ C_w, const float* __restrict__ E_w)
{
    int m0    = blockIdx.x * 32;
    int kbase = blockIdx.y * 128;
    int path  = blockIdx.z;
    const float* W = (path == 0 ? C_w : E_w) + 512*128;
    __shared__ float As[32][33];
    __shared__ float Bs[32][132];
    __shared__ int rowA[32], rowB[32];
    int tid = threadIdx.x;
    if (tid < 32) {
        int g = m0 + tid;
        int h = head_ids[g], t = tail_ids[g];
        rowA[tid] = (path == 0) ? h : t;
        rowB[tid] = (path == 0) ? t : h;
    }
    __syncthreads();
    int tx = tid & 31, ty = tid >> 5;   // tx: n/4, ty: m/4
    float acc[4][4] = {};
    for (int kc = 0; kc < 4; kc++) {
        int k0 = kbase + kc*32;
        for (int e = tid; e < 1024; e += 256) {
            int m = e >> 5, k = e & 31;
            int kg = k0 + k;
            int row = (kg < 512) ? rowA[m] : rowB[m];
            int kk  = (kg < 512) ? kg : kg - 512;
            As[m][k] = flat[(size_t)row*512 + kk];
        }
        for (int e = tid; e < 1024; e += 256) {
            int k = e >> 5, n = (e & 31) * 4;
            *(float4*)&Bs[k][n] = *(const float4*)&W[(size_t)(k0 + k)*128 + n];
        }
        __syncthreads();
        #pragma unroll
        for (int k = 0; k < 32; k++) {
            float4 b4 = *(const float4*)&Bs[k][tx*4];
            float a[4];
            #pragma unroll
            for (int i = 0; i < 4; i++) a[i] = As[ty*4 + i][k];
            #pragma unroll
            for (int i = 0; i < 4; i++) {
                acc[i][0] += a[i]*b4.x; acc[i][1] += a[i]*b4.y;
                acc[i][2] += a[i]*b4.z; acc[i][3] += a[i]*b4.w;
            }
        }
        __syncthreads();
    }
    #pragma unroll
    for (int i = 0; i < 4; i++)
        #pragma unroll
        for (int q = 0; q < 4; q++)
            g_PGpart[blockIdx.y][path][m0 + ty*4 + i][tx*4 + q] = acc[i][q];
}

// ---------------- kernel 3: fused pipeline (smem-free bf16 mainloop) ----
// smem float offsets
#define SW_OFF   0        // 1536
#define SB_OFF   1536     // 16
#define PG_OFF   1552     // 256
#define WSM_OFF  1808     // 1536
#define NUM_OFF  3344     // 1536
#define DEN_OFF  4880     // 16
#define PRJ_OFF  4896     // 512
#define LBL_OFF  5408     // 384 ints
#define SM_FLOATS 5792

__global__ __launch_bounds__(256, 2) void k_fused_mma(
    const float* __restrict__ flat,
    const float* __restrict__ head_sister, const float* __restrict__ tail_sister,
    const int* __restrict__ t_label, const int* __restrict__ hst, const int* __restrict__ tst,
    const float* __restrict__ B_w, const float* __restrict__ B_b,
    const float* __restrict__ Dm_w, const float* __restrict__ Dm_b,
    const float* __restrict__ G_w, const float* __restrict__ G_b)
{
    extern __shared__ float sm[];
    float* SW   = sm + SW_OFF;
    float* SB   = sm + SB_OFF;
    float* PG   = sm + PG_OFF;
    float* Wsm  = sm + WSM_OFF;
    float* NUM  = sm + NUM_OFF;
    float* DEN  = sm + DEN_OFF;
    float* PRJ  = sm + PRJ_OFF;
    int*   lbl  = (int*)(sm + LBL_OFF);

    const int b    = blockIdx.x;
    const int tid  = threadIdx.x;
    const int lane = tid & 31;
    const int wid  = tid >> 5;
    const int warpM = (wid & 3) * 32;
    const int warpN = (wid >> 2) * 64;
    const int qr = lane >> 2;
    const int qc = lane & 3;
    const int GlocBase = (wid & 3) * 2;        // warpM/16
    const int nbBase   = (wid >> 2) * 8;       // warpN/8

    for (int i = tid; i < 512; i += 256) {
        SW[i] = B_w[i]; SW[512 + i] = Dm_w[i]; SW[1024 + i] = G_w[i];
    }
    if (tid < 12) {
        int p = tid >> 2, l = tid & 3;
        SB[tid] = (p == 0) ? B_b[l] : ((p == 1) ? Dm_b[l] : G_b[l]);
        DEN[tid] = 0.f;
    }
    {
        int path = tid >> 7, col = tid & 127;
        float s = 0.f;
        #pragma unroll
        for (int q = 0; q < 8; q++) s += g_PGpart[q][path][b][col];
        PG[tid] = s;
    }
    for (int i = tid; i < 1536; i += 256) NUM[i] = 0.f;
    __syncthreads();

    for (int mt = 0; mt < 2; mt++) {
        const int rowbase = b*NPG + mt*128;
        const int Gbase = rowbase >> 4;
        if (tid < 128) {
            lbl[tid]       = t_label[rowbase + tid];
            lbl[128 + tid] = hst[rowbase + tid];
            lbl[256 + tid] = tst[rowbase + tid];
        }
        __syncthreads();

        const uint4* A0 = g_A + ((size_t)(Gbase + GlocBase)     * 32) * 32 + lane;
        const uint4* A1 = g_A + ((size_t)(Gbase + GlocBase + 1) * 32) * 32 + lane;

        for (int j = 0; j < 3; j++) {
            float acc[2][8][4];
            #pragma unroll
            for (int mi = 0; mi < 2; mi++)
                #pragma unroll
                for (int ni = 0; ni < 8; ni++)
                    #pragma unroll
                    for (int q = 0; q < 4; q++) acc[mi][ni][q] = 0.f;

            const uint4* Wj = g_Wt + (size_t)j*16*512 + (size_t)nbBase*32 + lane;

            for (int c = 0; c < 16; c++) {
                uint4 bv[8];
                #pragma unroll
                for (int ni = 0; ni < 8; ni++)
                    bv[ni] = Wj[(size_t)c*512 + ni*32];
                #pragma unroll
                for (int s = 0; s < 2; s++) {
                    uint4 av0 = A0[(2*c + s)*32];
                    uint4 av1 = A1[(2*c + s)*32];
                    uint32_t a0[4] = {av0.x, av0.y, av0.z, av0.w};
                    uint32_t a1[4] = {av1.x, av1.y, av1.z, av1.w};
                    #pragma unroll
                    for (int ni = 0; ni < 8; ni++) {
                        uint32_t b0 = s ? bv[ni].z : bv[ni].x;
                        uint32_t b1 = s ? bv[ni].w : bv[ni].y;
                        mma_bf16(acc[0][ni], a0, b0, b1);
                        mma_bf16(acc[1][ni], a1, b0, b1);
                    }
                }
            }
            __syncthreads();
            // init per-row projection accumulators with bias (all 512 entries)
            {
                float bvv = SB[j*4 + (tid & 3)];
                PRJ[tid]       = bvv;
                PRJ[tid + 256] = bvv;
            }
            __syncthreads();

            // epilogue: adds + ReLU + partial [*,4] projection, in registers
            #pragma unroll
            for (int mi = 0; mi < 2; mi++) {
                #pragma unroll
                for (int h = 0; h < 2; h++) {
                    int r = warpM + mi*16 + qr + h*8;
                    int lT = lbl[r], lH = lbl[128 + r], lS = lbl[256 + r];
                    float p0 = 0.f, p1 = 0.f, p2 = 0.f, p3 = 0.f;
                    #pragma unroll
                    for (int ni = 0; ni < 8; ni++) {
                        int col = warpN + ni*8 + qc*2;
                        float v0 = acc[mi][ni][h*2], v1 = acc[mi][ni][h*2 + 1];
                        float add0, add1;
                        if (j == 0) {
                            float2 t = *(const float2*)&g_tables[0][lT][col];
                            add0 = t.x; add1 = t.y;
                        } else if (j == 1) {
                            float2 t1 = *(const float2*)&g_tables[1][lH][col];
                            float2 t2 = *(const float2*)&g_tables[2][lT][col];
                            add0 = PG[col] + t1.x + t2.x;
                            add1 = PG[col + 1] + t1.y + t2.y;
                        } else {
                            float2 t1 = *(const float2*)&g_tables[3][lS][col];
                            float2 t2 = *(const float2*)&g_tables[4][lT][col];
                            add0 = PG[128 + col] + t1.x + t2.x;
                            add1 = PG[128 + col + 1] + t1.y + t2.y;
                        }
                        float H0 = fmaxf(v0 + add0, 0.f);
                        float H1 = fmaxf(v1 + add1, 0.f);
                        const float* w = SW + j*512 + col*4;
                        p0 += H0*w[0] + H1*w[4];
                        p1 += H0*w[1] + H1*w[5];
                        p2 += H0*w[2] + H1*w[6];
                        p3 += H0*w[3] + H1*w[7];
                    }
                    p0 += __shfl_xor_sync(0xffffffffu, p0, 1);
                    p0 += __shfl_xor_sync(0xffffffffu, p0, 2);
                    p1 += __shfl_xor_sync(0xffffffffu, p1, 1);
                    p1 += __shfl_xor_sync(0xffffffffu, p1, 2);
                    p2 += __shfl_xor_sync(0xffffffffu, p2, 1);
                    p2 += __shfl_xor_sync(0xffffffffu, p2, 2);
                    p3 += __shfl_xor_sync(0xffffffffu, p3, 1);
                    p3 += __shfl_xor_sync(0xffffffffu, p3, 2);
                    float pl = (qc == 0) ? p0 : ((qc == 1) ? p1 : ((qc == 2) ? p2 : p3));
                    atomicAdd(&PRJ[r*4 + qc], pl);
                }
            }
            __syncthreads();
            if (tid < 128) {
                int m = tid;
                float g0 = 1.f/(1.f + expf(-PRJ[m*4 + 0]));
                float g1 = 1.f/(1.f + expf(-PRJ[m*4 + 1]));
                float g2 = 1.f/(1.f + expf(-PRJ[m*4 + 2]));
                float g3 = 1.f/(1.f + expf(-PRJ[m*4 + 3]));
                if (j == 1) {
                    const float* hsv = head_sister + (size_t)(rowbase + m)*4;
                    g0 *= hsv[0]; g1 *= hsv[1]; g2 *= hsv[2]; g3 *= hsv[3];
                } else if (j == 2) {
                    const float* tsv = tail_sister + (size_t)(rowbase + m)*4;
                    g0 *= tsv[0]; g1 *= tsv[1]; g2 *= tsv[2]; g3 *= tsv[3];
                }
                float* wp = Wsm + (size_t)(j*128 + m)*4;
                wp[0] = g0; wp[1] = g1; wp[2] = g2; wp[3] = g3;
            }
            __syncthreads();
        }

        // weighted segment sums for this tile
        {
            int c0 = tid, c1 = tid + 256;
            int l0 = tid >> 7, l1 = l0 + 2;
            float s00=0,s01=0,s02=0, s10=0,s11=0,s12=0;
            for (int n = 0; n < 128; n++) {
                float v0 = flat[(size_t)(rowbase + n)*512 + c0];
                float v1 = flat[(size_t)(rowbase + n)*512 + c1];
                float w0 = Wsm[(0*128+n)*4 + l0], w1 = Wsm[(1*128+n)*4 + l0], w2 = Wsm[(2*128+n)*4 + l0];
                float x0 = Wsm[(0*128+n)*4 + l1], x1 = Wsm[(1*128+n)*4 + l1], x2 = Wsm[(2*128+n)*4 + l1];
                s00 += w0*v0; s01 += w1*v0; s02 += w2*v0;
                s10 += x0*v1; s11 += x1*v1; s12 += x2*v1;
            }
            NUM[0*512 + c0] += s00; NUM[1*512 + c0] += s01; NUM[2*512 + c0] += s02;
            NUM[0*512 + c1] += s10; NUM[1*512 + c1] += s11; NUM[2*512 + c1] += s12;
            if (tid < 12) {
                int p = tid >> 2, l = tid & 3;
                float s = 0.f;
                for (int n = 0; n < 128; n++) s += Wsm[(p*128 + n)*4 + l];
                DEN[tid] += s;
            }
        }
        __syncthreads();
    }

    {
        int c0 = tid, c1 = tid + 256;
        int l0 = tid >> 7, l1 = l0 + 2;
        #pragma unroll
        for (int p = 0; p < 3; p++) {
            g_gsum[b][p][c0] = NUM[p*512 + c0] / DEN[p*4 + l0];
            g_gsum[b][p][c1] = NUM[p*512 + c1] / DEN[p*4 + l1];
        }
    }
}

// ---------------- kernel 3.5: assemble g_ht rows ------------------------
__global__ void k_ght(const float* __restrict__ flat,
                      const int* __restrict__ head_ids, const int* __restrict__ tail_ids,
                      const int* __restrict__ rel_labels,
                      const float* __restrict__ she, const float* __restrict__ ste)
{
    int b = blockIdx.x, tid = threadIdx.x;
    int h = head_ids[b], t = tail_ids[b];
    float* out = g_ght[b];
    for (int c = tid; c < 512; c += 256) {
        float ghs = g_gsum[b][1][c], gts = g_gsum[b][2][c];
        float hv = flat[(size_t)h*512 + c], tv = flat[(size_t)t*512 + c];
        out[c]        = ghs * hv;
        out[512 + c]  = gts * tv;
        out[1024 + c] = ghs;
        out[1536 + c] = gts;
        out[2048 + c] = hv;
        out[2560 + c] = tv;
    }
    if (tid < 64) {
        int r = rel_labels[b];
        out[3072 + tid] = she[r*64 + tid];
        out[3136 + tid] = ste[r*64 + tid];
    }
}

// ---------------- kernel 4a: ht GEMM split-K 10 (partials) --------------
__global__ __launch_bounds__(256) void k_ht(const float* __restrict__ ht_w)
{
    __shared__ float As2[64][33], Bs2[32][65];
    int m0 = blockIdx.y*64, n0 = blockIdx.x*64, kbase = blockIdx.z*320;
    int tid = threadIdx.x, tx = tid & 15, ty = tid >> 4;
    float acc[4][4] = {};
    for (int kc = 0; kc < 10; kc++) {
        int k0 = kbase + kc*32;
        #pragma unroll
        for (int r = 0; r < 8; r++) {
            int e = r*256 + tid; int m = e >> 5, k = e & 31;
            As2[m][k] = g_ght[m0 + m][k0 + k];
        }
        #pragma unroll
        for (int r = 0; r < 8; r++) {
            int e = r*256 + tid; int k = e >> 6, n = e & 63;
            Bs2[k][n] = ht_w[(size_t)(k0 + k)*512 + n0 + n];
        }
        __syncthreads();
        #pragma unroll
        for (int k = 0; k < 32; k++) {
            float a[4], bv[4];
            #pragma unroll
            for (int i = 0; i < 4; i++) { a[i] = As2[ty*4 + i][k]; bv[i] = Bs2[k][tx*4 + i]; }
            #pragma unroll
            for (int i = 0; i < 4; i++)
                #pragma unroll
                for (int q = 0; q < 4; q++) acc[i][q] += a[i]*bv[q];
        }
        __syncthreads();
    }
    #pragma unroll
    for (int i = 0; i < 4; i++)
        #pragma unroll
        for (int q = 0; q < 4; q++)
            g_htacc[blockIdx.z][m0 + ty*4 + i][n0 + tx*4 + q] = acc[i][q];
}

// ---------------- kernel 4b: fc + out -----------------------------------
__global__ void k_final(const float* __restrict__ flat,
                        const int* __restrict__ head_ids, const int* __restrict__ tail_ids,
                        const int* __restrict__ rel_labels, const float* __restrict__ rel_emb,
                        const float* __restrict__ ht_b,
                        const float* __restrict__ fc_w, const float* __restrict__ fc_b,
                        const float* __restrict__ out_w, const float* __restrict__ out_b,
                        float* __restrict__ out)
{
    __shared__ float rep[2112];
    __shared__ float red[256][17];
    int b = blockIdx.x, tid = threadIdx.x;
    int h = head_ids[b], t = tail_ids[b];
    for (int c = tid; c < 512; c += 256) {
        rep[c]        = g_gsum[b][0][c];
        rep[512 + c]  = flat[(size_t)h*512 + c];
        rep[1024 + c] = flat[(size_t)t*512 + c];
        float s = 0.f;
        #pragma unroll
        for (int q = 0; q < 10; q++) s += g_htacc[q][b][c];
        rep[1536 + c] = fmaxf(s + ht_b[c], 0.f);
    }
    if (tid < 64) rep[2048 + tid] = rel_emb[rel_labels[b]*64 + tid];
    __syncthreads();

    float acc[16];
    #pragma unroll
    for (int j = 0; j < 16; j++) acc[j] = 0.f;
    for (int k = tid; k < 2112; k += 256) {
        float x = rep[k];
        const float4* w = (const float4*)(fc_w + (size_t)k*16);
        #pragma unroll
        for (int v = 0; v < 4; v++) {
            float4 ww = w[v];
            acc[v*4+0] += x*ww.x; acc[v*4+1] += x*ww.y;
            acc[v*4+2] += x*ww.z; acc[v*4+3] += x*ww.w;
        }
    }
    #pragma unroll
    for (int j = 0; j < 16; j++) red[tid][j] = acc[j];
    __syncthreads();
    for (int s = 128; s >= 1; s >>= 1) {
        if (tid < s) {
            #pragma unroll
            for (int j = 0; j < 16; j++) red[tid][j] += red[tid + s][j];
        }
        __syncthreads();
    }
    if (tid == 0) {
        float o = out_b[0];
        #pragma unroll
        for (int j = 0; j < 16; j++) o += fmaxf(red[0][j] + fc_b[j], 0.f) * out_w[j];
        out[b] = o;
    }
}

// ---------------- launch ------------------------------------------------
extern "C" void kernel_launch(void* const* d_in, const int* in_sizes, int n_in,
                              void* d_out, int out_size)
{
    const float* node_repr = (const float*)d_in[0];
    const float* head_sis  = (const float*)d_in[1];
    const float* tail_sis  = (const float*)d_in[2];
    const int*   t_label   = (const int*)d_in[3];
    const int*   hstp      = (const int*)d_in[4];
    const int*   tstp      = (const int*)d_in[5];
    const int*   head_ids  = (const int*)d_in[7];
    const int*   tail_ids  = (const int*)d_in[8];
    const int*   rel_lab   = (const int*)d_in[9];
    const float* rel_emb   = (const float*)d_in[10];
    const float* she       = (const float*)d_in[11];
    const float* ste       = (const float*)d_in[12];
    const float* A_w  = (const float*)d_in[13]; const float* A_b  = (const float*)d_in[14];
    const float* B_w  = (const float*)d_in[15]; const float* B_b  = (const float*)d_in[16];
    const float* C_w  = (const float*)d_in[17]; const float* C_b  = (const float*)d_in[18];
    const float* Dm_w = (const float*)d_in[19]; const float* Dm_b = (const float*)d_in[20];
    const float* E_w  = (const float*)d_in[21]; const float* E_b  = (const float*)d_in[22];
    const float* G_w  = (const float*)d_in[23]; const float* G_b  = (const float*)d_in[24];
    const float* ht_w = (const float*)d_in[25]; const float* ht_b = (const float*)d_in[26];
    const float* fc_w = (const float*)d_in[27]; const float* fc_b = (const float*)d_in[28];
    const float* out_w= (const float*)d_in[29]; const float* out_b= (const float*)d_in[30];
    float* out = (float*)d_out;

    const int smemBytes = SM_FLOATS * 4;
    cudaFuncSetAttribute(k_fused_mma, cudaFuncAttributeMaxDynamicSharedMemorySize, smemBytes);

    k_tables<<<dim3(Rr, 5), 128>>>(rel_emb, she, ste, A_w, A_b, C_w, C_b, E_w, E_b);
    k_prep<<<dim3(16, 3), 256>>>(A_w, C_w, E_w);
    k_aprep<<<8192, 256>>>(node_repr);
    k_pg<<<dim3(16, 8, 2), 256>>>(node_repr, head_ids, tail_ids, C_w, E_w);
    k_fused_mma<<<Bg, 256, smemBytes>>>(node_repr, head_sis, tail_sis, t_label, hstp, tstp,
                                        B_w, B_b, Dm_w, Dm_b, G_w, G_b);
    k_ght<<<Bg, 256>>>(node_repr, head_ids, tail_ids, rel_lab, she, ste);
    k_ht<<<dim3(8, 8, 10), 256>>>(ht_w);
    k_final<<<Bg, 256>>>(node_repr, head_ids, tail_ids, rel_lab, rel_emb, ht_b,
                         fc_w, fc_b, out_w, out_b, out);
}